// round 2
// baseline (speedup 1.0000x reference)
#include <cuda_runtime.h>
#include <math.h>

// ---------------------------------------------------------------------------
// Static scratch (no allocations allowed)
// ---------------------------------------------------------------------------
__device__ float g_col[67108864];   // max Cin*K*B*HW  (L2: 1024*16*4096)
__device__ float g_om [38535168];   // max 3K*B*HW     (L1: 147*16*16384)
__device__ float g_h  [16777216];   // current activation
__device__ float g_pre[16777216];   // pre-IN conv output
__device__ float g_y  [ 4194304];   // residual branch

#define THREADS 256

// ---------------------------------------------------------------------------
// Plain im2col (integer sampling, zero pad) : col[b][ci*K+k][pos]
// ---------------------------------------------------------------------------
__global__ void build_cols_plain(const float* __restrict__ x, float* __restrict__ col,
                                 int B, int Cin, int H, int W,
                                 int kh, int kw, int stride, int pad,
                                 int Ho, int Wo) {
    int K = kh * kw;
    int HW = Ho * Wo;
    int total = B * Cin * K * HW;
    int t = blockIdx.x * THREADS + threadIdx.x;
    if (t >= total) return;
    int pos = t % HW;
    int rest = t / HW;
    int ck = rest % (Cin * K);
    int b  = rest / (Cin * K);
    int k  = ck % K;
    int ci = ck / K;
    int ho = pos / Wo, wo = pos % Wo;
    int iy = ho * stride - pad + (k / kw);
    int ix = wo * stride - pad + (k % kw);
    float v = 0.f;
    if (iy >= 0 && iy < H && ix >= 0 && ix < W)
        v = x[(((size_t)b * Cin + ci) * H + iy) * W + ix];
    col[t] = v;
}

// ---------------------------------------------------------------------------
// Deformable im2col: bilinear sample at base+offset, times sigmoid(mask)
// om layout [B][3K][Ho*Wo]; off_y = om[2k], off_x = om[2k+1], mask = om[2K+k]
// ---------------------------------------------------------------------------
__global__ void build_cols_deform(const float* __restrict__ x, const float* __restrict__ om,
                                  float* __restrict__ col,
                                  int B, int Cin, int H, int W,
                                  int kh, int kw, int stride, int pad,
                                  int Ho, int Wo) {
    int K = kh * kw;
    int HW = Ho * Wo;
    int total = B * K * HW;
    int t = blockIdx.x * THREADS + threadIdx.x;
    if (t >= total) return;
    int pos = t % HW;
    int bk = t / HW;
    int k = bk % K;
    int b = bk / K;
    int ho = pos / Wo, wo = pos % Wo;

    const float* omb = om + (size_t)b * 3 * K * HW;
    float offy = omb[(size_t)(2 * k) * HW + pos];
    float offx = omb[(size_t)(2 * k + 1) * HW + pos];
    float mk   = omb[(size_t)(2 * K + k) * HW + pos];
    mk = 1.f / (1.f + expf(-mk));

    float yf = (float)(ho * stride - pad + k / kw) + offy;
    float xf = (float)(wo * stride - pad + k % kw) + offx;
    float y0f = floorf(yf), x0f = floorf(xf);
    float dy = yf - y0f, dx = xf - x0f;
    int y0 = (int)y0f, x0 = (int)x0f;
    int y1 = y0 + 1, x1 = x0 + 1;

    float w00 = (1.f - dy) * (1.f - dx) * mk;
    float w01 = (1.f - dy) * dx * mk;
    float w10 = dy * (1.f - dx) * mk;
    float w11 = dy * dx * mk;
    bool vy0 = (y0 >= 0) && (y0 < H);
    bool vy1 = (y1 >= 0) && (y1 < H);
    bool vx0 = (x0 >= 0) && (x0 < W);
    bool vx1 = (x1 >= 0) && (x1 < W);

    const float* xb = x + (size_t)b * Cin * H * W;
    float* cb = col + ((size_t)b * Cin * K) * HW + (size_t)k * HW + pos;
    size_t plane = (size_t)H * W;
    size_t cstride = (size_t)K * HW;
    for (int ci = 0; ci < Cin; ci++) {
        const float* xp = xb + (size_t)ci * plane;
        float v = 0.f;
        if (vy0 && vx0) v += w00 * xp[y0 * W + x0];
        if (vy0 && vx1) v += w01 * xp[y0 * W + x1];
        if (vy1 && vx0) v += w10 * xp[y1 * W + x0];
        if (vy1 && vx1) v += w11 * xp[y1 * W + x1];
        cb[(size_t)ci * cstride] = v;
    }
}

// ---------------------------------------------------------------------------
// Batched SGEMM with bias: C[b][m][n] = sum_k A[m][k] * Bm[b][k][n] + bias[m]
// 64x64 tile, TK=16, 16x16 threads, 4x4 micro-tile. N multiple of 64.
// ---------------------------------------------------------------------------
#define TM 64
#define TN 64
#define TK 16
__global__ void gemm_bias(const float* __restrict__ A, const float* __restrict__ Bm,
                          const float* __restrict__ bias, float* __restrict__ C,
                          int M, int Kd, int N) {
    int b = blockIdx.z;
    const float* Bb = Bm + (size_t)b * Kd * N;
    float* Cb = C + (size_t)b * M * N;
    int tile_m = blockIdx.y * TM;
    int tile_n = blockIdx.x * TN;

    __shared__ float As[TK][TM];
    __shared__ float Bs[TK][TN + 1];

    int tid = threadIdx.y * 16 + threadIdx.x;
    int mrow = threadIdx.y * 4;
    int ncol = threadIdx.x * 4;

    float acc[4][4];
#pragma unroll
    for (int i = 0; i < 4; i++)
#pragma unroll
        for (int j = 0; j < 4; j++) acc[i][j] = 0.f;

    for (int k0 = 0; k0 < Kd; k0 += TK) {
#pragma unroll
        for (int i = 0; i < 4; i++) {
            int idx = tid + i * 256;              // 0..1023
            // A tile: As[kk][m]
            int m  = idx / TK;
            int kk = idx % TK;
            int gm = tile_m + m, gk = k0 + kk;
            As[kk][m] = (gm < M && gk < Kd) ? A[(size_t)gm * Kd + gk] : 0.f;
            // B tile: Bs[kb][n]
            int n  = idx % TN;
            int kb = idx / TN;
            int gkb = k0 + kb;
            Bs[kb][n] = (gkb < Kd) ? Bb[(size_t)gkb * N + tile_n + n] : 0.f;
        }
        __syncthreads();
#pragma unroll
        for (int kk = 0; kk < TK; kk++) {
            float a[4], bv[4];
#pragma unroll
            for (int i = 0; i < 4; i++) a[i] = As[kk][mrow + i];
#pragma unroll
            for (int j = 0; j < 4; j++) bv[j] = Bs[kk][ncol + j];
#pragma unroll
            for (int i = 0; i < 4; i++)
#pragma unroll
                for (int j = 0; j < 4; j++) acc[i][j] += a[i] * bv[j];
        }
        __syncthreads();
    }

#pragma unroll
    for (int i = 0; i < 4; i++) {
        int gm = tile_m + mrow + i;
        if (gm >= M) continue;
        float bb = bias[gm];
#pragma unroll
        for (int j = 0; j < 4; j++)
            Cb[(size_t)gm * N + tile_n + ncol + j] = acc[i][j] + bb;
    }
}

// ---------------------------------------------------------------------------
// InstanceNorm over HW per (b,c) plane. Optional relu / residual add / 2nd dst.
// ---------------------------------------------------------------------------
__global__ void instnorm(const float* __restrict__ in, float* __restrict__ out,
                         float* __restrict__ out2, const float* __restrict__ addsrc,
                         int HW, int relu) {
    int plane = blockIdx.x;
    const float* p = in + (size_t)plane * HW;
    __shared__ float ssum[THREADS];
    __shared__ float ssq[THREADS];
    int tid = threadIdx.x;
    float s = 0.f, sq = 0.f;
    for (int i = tid; i < HW; i += THREADS) {
        float v = p[i];
        s += v; sq += v * v;
    }
    ssum[tid] = s; ssq[tid] = sq;
    __syncthreads();
    for (int off = THREADS / 2; off > 0; off >>= 1) {
        if (tid < off) { ssum[tid] += ssum[tid + off]; ssq[tid] += ssq[tid + off]; }
        __syncthreads();
    }
    __shared__ float mu_s, rs_s;
    if (tid == 0) {
        float mu = ssum[0] / (float)HW;
        float var = ssq[0] / (float)HW - mu * mu;
        mu_s = mu;
        rs_s = rsqrtf(var + 1e-5f);
    }
    __syncthreads();
    float mu = mu_s, rs = rs_s;
    float* o = out + (size_t)plane * HW;
    for (int i = tid; i < HW; i += THREADS) {
        float v = (p[i] - mu) * rs;
        if (relu) v = fmaxf(v, 0.f);
        if (addsrc) v += addsrc[(size_t)plane * HW + i];
        o[i] = v;
        if (out2) out2[(size_t)plane * HW + i] = v;
    }
}

// ---------------------------------------------------------------------------
// 3x3 conv, reflect pad 1, 32x32 planes, Cout chunk of 8 per block.
// grid = (B, Cout/8), block = 256. Each thread: 4 pixels x 8 co.
// ---------------------------------------------------------------------------
__global__ void conv3_reflect_k(const float* __restrict__ x, const float* __restrict__ w,
                                const float* __restrict__ bias, float* __restrict__ out,
                                int Cin, int Cout) {
    int b = blockIdx.x;
    int co0 = blockIdx.y * 8;
    __shared__ float xs[34 * 34];
    __shared__ float ws[8][9];
    int tid = threadIdx.x;

    float acc[8][4];
#pragma unroll
    for (int c = 0; c < 8; c++)
#pragma unroll
        for (int p = 0; p < 4; p++) acc[c][p] = 0.f;

    for (int ci = 0; ci < Cin; ci++) {
        const float* xp = x + ((size_t)b * Cin + ci) * 1024;
        for (int idx = tid; idx < 34 * 34; idx += 256) {
            int py = idx / 34 - 1, px = idx % 34 - 1;
            int iy = py < 0 ? -py : (py > 31 ? 62 - py : py);
            int ix = px < 0 ? -px : (px > 31 ? 62 - px : px);
            xs[idx] = xp[iy * 32 + ix];
        }
        if (tid < 72)
            ws[tid / 9][tid % 9] = w[((size_t)(co0 + tid / 9) * Cin + ci) * 9 + tid % 9];
        __syncthreads();

#pragma unroll
        for (int pp = 0; pp < 4; pp++) {
            int p = tid + pp * 256;
            int yy = p >> 5, xx = p & 31;
            float v[9];
#pragma unroll
            for (int dy = 0; dy < 3; dy++)
#pragma unroll
                for (int dx = 0; dx < 3; dx++)
                    v[dy * 3 + dx] = xs[(yy + dy) * 34 + (xx + dx)];
#pragma unroll
            for (int c = 0; c < 8; c++) {
                float a = 0.f;
#pragma unroll
                for (int q = 0; q < 9; q++) a += v[q] * ws[c][q];
                acc[c][pp] += a;
            }
        }
        __syncthreads();
    }

#pragma unroll
    for (int c = 0; c < 8; c++) {
        float bb = bias[co0 + c];
#pragma unroll
        for (int pp = 0; pp < 4; pp++)
            out[((size_t)b * Cout + co0 + c) * 1024 + tid + pp * 256] = acc[c][pp] + bb;
    }
}

// ---------------------------------------------------------------------------
// Host orchestration
// ---------------------------------------------------------------------------
static inline int ceil_div(int a, int b) { return (a + b - 1) / b; }

extern "C" void kernel_launch(void* const* d_in, const int* in_sizes, int n_in,
                              void* d_out, int out_size) {
    (void)in_sizes; (void)n_in; (void)out_size;
    const float* x      = (const float*)d_in[0];
    const float* w_off1 = (const float*)d_in[1];
    const float* b_off1 = (const float*)d_in[2];
    const float* w1     = (const float*)d_in[3];
    const float* b1     = (const float*)d_in[4];
    const float* w_off2 = (const float*)d_in[5];
    const float* b_off2 = (const float*)d_in[6];
    const float* w2     = (const float*)d_in[7];
    const float* b2     = (const float*)d_in[8];
    const float* w_off3 = (const float*)d_in[9];
    const float* b_off3 = (const float*)d_in[10];
    const float* w3     = (const float*)d_in[11];
    const float* b3     = (const float*)d_in[12];
    const float* rw0a   = (const float*)d_in[13];
    const float* rb0a   = (const float*)d_in[14];
    const float* rw0b   = (const float*)d_in[15];
    const float* rb0b   = (const float*)d_in[16];
    const float* rw1a   = (const float*)d_in[17];
    const float* rb1a   = (const float*)d_in[18];
    const float* rw1b   = (const float*)d_in[19];
    const float* rb1b   = (const float*)d_in[20];
    float* out = (float*)d_out;

    float *col, *om, *h, *pre, *yb;
    cudaGetSymbolAddress((void**)&col, g_col);
    cudaGetSymbolAddress((void**)&om,  g_om);
    cudaGetSymbolAddress((void**)&h,   g_h);
    cudaGetSymbolAddress((void**)&pre, g_pre);
    cudaGetSymbolAddress((void**)&yb,  g_y);

    const int B = 16;
    dim3 tb16(16, 16);

    // ---------------- Layer 1: 3 -> 64, 7x7 s1 p3, 128x128 -> 128x128 ------
    {
        int Cin = 3, H = 128, W = 128, kh = 7, kw = 7, s = 1, p = 3;
        int Ho = 128, Wo = 128, K = 49, CK = 147, Coff = 147, Cout = 64, HW = Ho * Wo;
        build_cols_plain<<<ceil_div(B * CK * HW, THREADS), THREADS>>>(
            x, col, B, Cin, H, W, kh, kw, s, p, Ho, Wo);
        gemm_bias<<<dim3(HW / TN, ceil_div(Coff, TM), B), tb16>>>(
            w_off1, col, b_off1, om, Coff, CK, HW);
        build_cols_deform<<<ceil_div(B * K * HW, THREADS), THREADS>>>(
            x, om, col, B, Cin, H, W, kh, kw, s, p, Ho, Wo);
        gemm_bias<<<dim3(HW / TN, ceil_div(Cout, TM), B), tb16>>>(
            w1, col, b1, pre, Cout, CK, HW);
        instnorm<<<B * Cout, THREADS>>>(pre, h, nullptr, nullptr, HW, 1);
    }
    // ---------------- Layer 2: 64 -> 128, 4x4 s2 p1, 128 -> 64 -------------
    {
        int Cin = 64, H = 128, W = 128, kh = 4, kw = 4, s = 2, p = 1;
        int Ho = 64, Wo = 64, K = 16, CK = 1024, Coff = 48, Cout = 128, HW = Ho * Wo;
        build_cols_plain<<<ceil_div(B * CK * HW, THREADS), THREADS>>>(
            h, col, B, Cin, H, W, kh, kw, s, p, Ho, Wo);
        gemm_bias<<<dim3(HW / TN, ceil_div(Coff, TM), B), tb16>>>(
            w_off2, col, b_off2, om, Coff, CK, HW);
        build_cols_deform<<<ceil_div(B * K * HW, THREADS), THREADS>>>(
            h, om, col, B, Cin, H, W, kh, kw, s, p, Ho, Wo);
        gemm_bias<<<dim3(HW / TN, ceil_div(Cout, TM), B), tb16>>>(
            w2, col, b2, pre, Cout, CK, HW);
        instnorm<<<B * Cout, THREADS>>>(pre, h, out + 4194304, nullptr, HW, 1);  // skip2
    }
    // ---------------- Layer 3: 128 -> 256, 4x4 s2 p1, 64 -> 32 -------------
    {
        int Cin = 128, H = 64, W = 64, kh = 4, kw = 4, s = 2, p = 1;
        int Ho = 32, Wo = 32, K = 16, CK = 2048, Coff = 48, Cout = 256, HW = Ho * Wo;
        build_cols_plain<<<ceil_div(B * CK * HW, THREADS), THREADS>>>(
            h, col, B, Cin, H, W, kh, kw, s, p, Ho, Wo);
        gemm_bias<<<dim3(HW / TN, ceil_div(Coff, TM), B), tb16>>>(
            w_off3, col, b_off3, om, Coff, CK, HW);
        build_cols_deform<<<ceil_div(B * K * HW, THREADS), THREADS>>>(
            h, om, col, B, Cin, H, W, kh, kw, s, p, Ho, Wo);
        gemm_bias<<<dim3(HW / TN, ceil_div(Cout, TM), B), tb16>>>(
            w3, col, b3, pre, Cout, CK, HW);
        instnorm<<<B * Cout, THREADS>>>(pre, h, out + 12582912, nullptr, HW, 1); // skip3
    }
    // ---------------- Residual blocks (256ch, 32x32) ------------------------
    {
        const int HW = 1024, C = 256;
        const float* wa[2] = { rw0a, rw1a };
        const float* ba[2] = { rb0a, rb1a };
        const float* wb[2] = { rw0b, rw1b };
        const float* bbv[2] = { rb0b, rb1b };
        for (int r = 0; r < 2; r++) {
            conv3_reflect_k<<<dim3(B, C / 8), THREADS>>>(h, wa[r], ba[r], pre, C, C);
            instnorm<<<B * C, THREADS>>>(pre, yb, nullptr, nullptr, HW, 1);
            conv3_reflect_k<<<dim3(B, C / 8), THREADS>>>(yb, wb[r], bbv[r], pre, C, C);
            float* dst = (r == 0) ? h : out;   // final h goes straight to d_out
            instnorm<<<B * C, THREADS>>>(pre, dst, nullptr, h, HW, 0);
        }
    }
}

// round 3
// speedup vs baseline: 1.8018x; 1.8018x over previous
#include <cuda_runtime.h>
#include <math.h>

// ---------------------------------------------------------------------------
// Static scratch (no allocations allowed)
// ---------------------------------------------------------------------------
__device__ float g_col[67108864];   // im2col buffer (max 160*16*16384 = 41.9M, L2: 67M)
__device__ float g_om [38535168];   // offset/mask maps (max 147*16*16384)
__device__ float g_h  [16777216];   // current activation
__device__ float g_pre[16777216];   // pre-IN conv output
__device__ float g_y  [ 4194304];   // residual branch
__device__ float g_wpadA[147 * 160];  // padded w_off1
__device__ float g_wpadB[ 64 * 160];  // padded w1

#define THREADS 256

// ---------------------------------------------------------------------------
// Pad weight rows K -> Kp with zeros (row-major [M][K] -> [M][Kp])
// ---------------------------------------------------------------------------
__global__ void pad_rows(const float* __restrict__ src, float* __restrict__ dst,
                         int M, int K, int Kp) {
    int t = blockIdx.x * THREADS + threadIdx.x;
    if (t >= M * Kp) return;
    int m = t / Kp, k = t % Kp;
    dst[t] = (k < K) ? src[m * K + k] : 0.f;
}

// ---------------------------------------------------------------------------
// Zero pad rows [CK, CKp) of col buffer, per batch
// ---------------------------------------------------------------------------
__global__ void zero_pad_rows(float* __restrict__ col, int B, int CK, int CKp, int HW) {
    int rows = CKp - CK;
    int t = blockIdx.x * THREADS + threadIdx.x;
    int total = B * rows * HW;
    if (t >= total) return;
    int pos = t % HW;
    int rest = t / HW;
    int r = rest % rows;
    int b = rest / rows;
    col[((size_t)b * CKp + CK + r) * HW + pos] = 0.f;
}

// ---------------------------------------------------------------------------
// Plain im2col (integer sampling, zero pad) : col[b][ci*K+k][pos], CKp stride
// ---------------------------------------------------------------------------
__global__ void build_cols_plain(const float* __restrict__ x, float* __restrict__ col,
                                 int B, int Cin, int H, int W,
                                 int kh, int kw, int stride, int pad,
                                 int Ho, int Wo, int CK, int CKp) {
    int K = kh * kw;
    int HW = Ho * Wo;
    int total = B * CKp * HW;
    int t = blockIdx.x * THREADS + threadIdx.x;
    if (t >= total) return;
    int pos = t % HW;
    int rest = t / HW;
    int ck = rest % CKp;
    int b  = rest / CKp;
    float v = 0.f;
    if (ck < CK) {
        int k  = ck % K;
        int ci = ck / K;
        int ho = pos / Wo, wo = pos % Wo;
        int iy = ho * stride - pad + (k / kw);
        int ix = wo * stride - pad + (k % kw);
        if (iy >= 0 && iy < H && ix >= 0 && ix < W)
            v = x[(((size_t)b * Cin + ci) * H + iy) * W + ix];
    }
    col[t] = v;
}

// ---------------------------------------------------------------------------
// Deformable im2col: bilinear sample at base+offset, times sigmoid(mask)
// om layout [B][3K][Ho*Wo]; off_y = om[2k], off_x = om[2k+1], mask = om[2K+k]
// col stride uses CKp rows per batch.
// ---------------------------------------------------------------------------
__global__ void build_cols_deform(const float* __restrict__ x, const float* __restrict__ om,
                                  float* __restrict__ col,
                                  int B, int Cin, int H, int W,
                                  int kh, int kw, int stride, int pad,
                                  int Ho, int Wo, int CKp) {
    int K = kh * kw;
    int HW = Ho * Wo;
    int total = B * K * HW;
    int t = blockIdx.x * THREADS + threadIdx.x;
    if (t >= total) return;
    int pos = t % HW;
    int bk = t / HW;
    int k = bk % K;
    int b = bk / K;
    int ho = pos / Wo, wo = pos % Wo;

    const float* omb = om + (size_t)b * 3 * K * HW;
    float offy = omb[(size_t)(2 * k) * HW + pos];
    float offx = omb[(size_t)(2 * k + 1) * HW + pos];
    float mk   = omb[(size_t)(2 * K + k) * HW + pos];
    mk = 1.f / (1.f + expf(-mk));

    float yf = (float)(ho * stride - pad + k / kw) + offy;
    float xf = (float)(wo * stride - pad + k % kw) + offx;
    float y0f = floorf(yf), x0f = floorf(xf);
    float dy = yf - y0f, dx = xf - x0f;
    int y0 = (int)y0f, x0 = (int)x0f;
    int y1 = y0 + 1, x1 = x0 + 1;

    float w00 = (1.f - dy) * (1.f - dx) * mk;
    float w01 = (1.f - dy) * dx * mk;
    float w10 = dy * (1.f - dx) * mk;
    float w11 = dy * dx * mk;
    bool vy0 = (y0 >= 0) && (y0 < H);
    bool vy1 = (y1 >= 0) && (y1 < H);
    bool vx0 = (x0 >= 0) && (x0 < W);
    bool vx1 = (x1 >= 0) && (x1 < W);

    const float* xb = x + (size_t)b * Cin * H * W;
    float* cb = col + ((size_t)b * CKp + k) * HW + pos;
    size_t plane = (size_t)H * W;
    size_t cstride = (size_t)K * HW;
    for (int ci = 0; ci < Cin; ci++) {
        const float* xp = xb + (size_t)ci * plane;
        float v = 0.f;
        if (vy0 && vx0) v += w00 * xp[y0 * W + x0];
        if (vy0 && vx1) v += w01 * xp[y0 * W + x1];
        if (vy1 && vx0) v += w10 * xp[y1 * W + x0];
        if (vy1 && vx1) v += w11 * xp[y1 * W + x1];
        cb[(size_t)ci * cstride] = v;
    }
}

// ---------------------------------------------------------------------------
// Reflect-pad im2col for 3x3 conv on 32x32 planes: col[b][ci*9+k][1024]
// ---------------------------------------------------------------------------
__global__ void build_cols_reflect(const float* __restrict__ x, float* __restrict__ col,
                                   int B, int Cin) {
    const int HW = 1024;
    int CK = Cin * 9;
    int total = B * CK * HW;
    int t = blockIdx.x * THREADS + threadIdx.x;
    if (t >= total) return;
    int pos = t % HW;
    int rest = t / HW;
    int ck = rest % CK;
    int b  = rest / CK;
    int k  = ck % 9;
    int ci = ck / 9;
    int ho = pos >> 5, wo = pos & 31;
    int iy = ho - 1 + k / 3;
    int ix = wo - 1 + k % 3;
    iy = iy < 0 ? -iy : (iy > 31 ? 62 - iy : iy);
    ix = ix < 0 ? -ix : (ix > 31 ? 62 - ix : ix);
    col[t] = x[(((size_t)b * Cin + ci) << 10) + iy * 32 + ix];
}

// ---------------------------------------------------------------------------
// Batched GEMM with bias using packed fp32x2 FMA (FFMA2, sm_10x only).
// C[b][m][n] = sum_k A[m][k] * Bcol[b][k][n] + bias[m]
// BM x 128 tile, BK=16, 256 threads, (BM/16) x 8 micro-tile per thread.
// Requirements: Kp % 16 == 0, N % 128 == 0.
// ---------------------------------------------------------------------------
#define BN 128
#define BKK 16

template <int BM>
__global__ void __launch_bounds__(256, 2)
gemm_f32x2(const float* __restrict__ A, const float* __restrict__ Bcol,
           const float* __restrict__ bias, float* __restrict__ C,
           int M, int Kp, int N) {
    constexpr int RM = BM / 16;  // rows per thread: 8 (BM=128) or 4 (BM=64)
    int b = blockIdx.z;
    const float* Bb = Bcol + (size_t)b * Kp * N;
    float* Cb = C + (size_t)b * M * N;
    int tM = blockIdx.y * BM;
    int tN = blockIdx.x * BN;

    __shared__ float As[BKK][BM];
    __shared__ float Bs[BKK][BN];

    int tid = threadIdx.x;
    int tx = tid & 15;   // column group: cols tx*4..tx*4+3 and +64
    int ty = tid >> 4;   // row group:    rows ty*4..ty*4+3 (and +64 if BM=128)

    unsigned long long acc[RM][4];
#pragma unroll
    for (int i = 0; i < RM; i++)
#pragma unroll
        for (int j = 0; j < 4; j++) acc[i][j] = 0ULL;

    for (int k0 = 0; k0 < Kp; k0 += BKK) {
        // ---- load A tile (BM x 16), store transposed As[k][m] ----
#pragma unroll
        for (int it = 0; it < BM / 64; it++) {
            int f4 = tid + it * 256;
            int m  = f4 >> 2;
            int kq = (f4 & 3) * 4;
            float4 v = make_float4(0.f, 0.f, 0.f, 0.f);
            int gm = tM + m;
            if (gm < M) v = *(const float4*)&A[(size_t)gm * Kp + k0 + kq];
            As[kq + 0][m] = v.x;
            As[kq + 1][m] = v.y;
            As[kq + 2][m] = v.z;
            As[kq + 3][m] = v.w;
        }
        // ---- load B tile (16 x 128) ----
#pragma unroll
        for (int it = 0; it < 2; it++) {
            int f4 = tid + it * 256;
            int row = f4 >> 5;
            int c4  = (f4 & 31) * 4;
            *(float4*)&Bs[row][c4] =
                *(const float4*)&Bb[(size_t)(k0 + row) * N + tN + c4];
        }
        __syncthreads();

#pragma unroll
        for (int kk = 0; kk < BKK; kk++) {
            // b fragment as packed f32x2 pairs (no repack needed: reg pairs)
            double2 blo = *(const double2*)&Bs[kk][tx * 4];
            double2 bhi = *(const double2*)&Bs[kk][tx * 4 + 64];
            unsigned long long bp[4];
            bp[0] = __double_as_longlong(blo.x);
            bp[1] = __double_as_longlong(blo.y);
            bp[2] = __double_as_longlong(bhi.x);
            bp[3] = __double_as_longlong(bhi.y);

            // a fragment, duplicated into both f32x2 lanes
            float4 a0 = *(const float4*)&As[kk][ty * 4];
            float av[RM];
            av[0] = a0.x; av[1] = a0.y; av[2] = a0.z; av[3] = a0.w;
            if (BM == 128) {
                float4 a1 = *(const float4*)&As[kk][ty * 4 + 64];
                av[4] = a1.x; av[5] = a1.y; av[6] = a1.z; av[7] = a1.w;
            }
            unsigned long long ad[RM];
#pragma unroll
            for (int i = 0; i < RM; i++)
                asm("mov.b64 %0, {%1, %1};" : "=l"(ad[i]) : "f"(av[i]));

#pragma unroll
            for (int i = 0; i < RM; i++)
#pragma unroll
                for (int j = 0; j < 4; j++)
                    asm("fma.rn.f32x2 %0, %1, %2, %0;"
                        : "+l"(acc[i][j]) : "l"(ad[i]), "l"(bp[j]));
        }
        __syncthreads();
    }

    // ---- epilogue: unpack, add bias, store ----
#pragma unroll
    for (int i = 0; i < RM; i++) {
        int gm = tM + ((i < 4) ? (ty * 4 + i) : (64 + ty * 4 + (i - 4)));
        if (gm >= M) continue;
        float bb = bias[gm];
        float o[8];
#pragma unroll
        for (int j = 0; j < 4; j++)
            asm("mov.b64 {%0, %1}, %2;"
                : "=f"(o[2 * j]), "=f"(o[2 * j + 1]) : "l"(acc[i][j]));
        float4 s0 = make_float4(o[0] + bb, o[1] + bb, o[2] + bb, o[3] + bb);
        float4 s1 = make_float4(o[4] + bb, o[5] + bb, o[6] + bb, o[7] + bb);
        *(float4*)&Cb[(size_t)gm * N + tN + tx * 4]      = s0;
        *(float4*)&Cb[(size_t)gm * N + tN + tx * 4 + 64] = s1;
    }
}

// ---------------------------------------------------------------------------
// InstanceNorm over HW per (b,c) plane. Optional relu / residual add / 2nd dst.
// ---------------------------------------------------------------------------
__global__ void instnorm(const float* __restrict__ in, float* __restrict__ out,
                         float* __restrict__ out2, const float* __restrict__ addsrc,
                         int HW, int relu) {
    int plane = blockIdx.x;
    const float* p = in + (size_t)plane * HW;
    __shared__ float ssum[THREADS];
    __shared__ float ssq[THREADS];
    int tid = threadIdx.x;
    float s = 0.f, sq = 0.f;
    for (int i = tid; i < HW; i += THREADS) {
        float v = p[i];
        s += v; sq += v * v;
    }
    ssum[tid] = s; ssq[tid] = sq;
    __syncthreads();
    for (int off = THREADS / 2; off > 0; off >>= 1) {
        if (tid < off) { ssum[tid] += ssum[tid + off]; ssq[tid] += ssq[tid + off]; }
        __syncthreads();
    }
    __shared__ float mu_s, rs_s;
    if (tid == 0) {
        float mu = ssum[0] / (float)HW;
        float var = ssq[0] / (float)HW - mu * mu;
        mu_s = mu;
        rs_s = rsqrtf(var + 1e-5f);
    }
    __syncthreads();
    float mu = mu_s, rs = rs_s;
    float* o = out + (size_t)plane * HW;
    for (int i = tid; i < HW; i += THREADS) {
        float v = (p[i] - mu) * rs;
        if (relu) v = fmaxf(v, 0.f);
        if (addsrc) v += addsrc[(size_t)plane * HW + i];
        o[i] = v;
        if (out2) out2[(size_t)plane * HW + i] = v;
    }
}

// ---------------------------------------------------------------------------
// Host orchestration
// ---------------------------------------------------------------------------
static inline int ceil_div(int a, int b) { return (a + b - 1) / b; }

extern "C" void kernel_launch(void* const* d_in, const int* in_sizes, int n_in,
                              void* d_out, int out_size) {
    (void)in_sizes; (void)n_in; (void)out_size;
    const float* x      = (const float*)d_in[0];
    const float* w_off1 = (const float*)d_in[1];
    const float* b_off1 = (const float*)d_in[2];
    const float* w1     = (const float*)d_in[3];
    const float* b1     = (const float*)d_in[4];
    const float* w_off2 = (const float*)d_in[5];
    const float* b_off2 = (const float*)d_in[6];
    const float* w2     = (const float*)d_in[7];
    const float* b2     = (const float*)d_in[8];
    const float* w_off3 = (const float*)d_in[9];
    const float* b_off3 = (const float*)d_in[10];
    const float* w3     = (const float*)d_in[11];
    const float* b3     = (const float*)d_in[12];
    const float* rw0a   = (const float*)d_in[13];
    const float* rb0a   = (const float*)d_in[14];
    const float* rw0b   = (const float*)d_in[15];
    const float* rb0b   = (const float*)d_in[16];
    const float* rw1a   = (const float*)d_in[17];
    const float* rb1a   = (const float*)d_in[18];
    const float* rw1b   = (const float*)d_in[19];
    const float* rb1b   = (const float*)d_in[20];
    float* out = (float*)d_out;

    float *col, *om, *h, *pre, *yb, *wpA, *wpB;
    cudaGetSymbolAddress((void**)&col, g_col);
    cudaGetSymbolAddress((void**)&om,  g_om);
    cudaGetSymbolAddress((void**)&h,   g_h);
    cudaGetSymbolAddress((void**)&pre, g_pre);
    cudaGetSymbolAddress((void**)&yb,  g_y);
    cudaGetSymbolAddress((void**)&wpA, g_wpadA);
    cudaGetSymbolAddress((void**)&wpB, g_wpadB);

    const int B = 16;

    // ---------------- Layer 1: 3 -> 64, 7x7 s1 p3, 128x128 -> 128x128 ------
    {
        int Cin = 3, H = 128, W = 128, kh = 7, kw = 7, s = 1, p = 3;
        int Ho = 128, Wo = 128, K = 49, CK = 147, CKp = 160, HW = Ho * Wo;
        pad_rows<<<ceil_div(147 * 160, THREADS), THREADS>>>(w_off1, wpA, 147, 147, 160);
        pad_rows<<<ceil_div(64 * 160, THREADS), THREADS>>>(w1, wpB, 64, 147, 160);
        build_cols_plain<<<ceil_div(B * CKp * HW, THREADS), THREADS>>>(
            x, col, B, Cin, H, W, kh, kw, s, p, Ho, Wo, CK, CKp);
        gemm_f32x2<128><<<dim3(HW / BN, 2, B), 256>>>(wpA, col, b_off1, om, 147, CKp, HW);
        build_cols_deform<<<ceil_div(B * K * HW, THREADS), THREADS>>>(
            x, om, col, B, Cin, H, W, kh, kw, s, p, Ho, Wo, CKp);
        zero_pad_rows<<<ceil_div(B * (CKp - CK) * HW, THREADS), THREADS>>>(col, B, CK, CKp, HW);
        gemm_f32x2<64><<<dim3(HW / BN, 1, B), 256>>>(wpB, col, b1, pre, 64, CKp, HW);
        instnorm<<<B * 64, THREADS>>>(pre, h, nullptr, nullptr, HW, 1);
    }
    // ---------------- Layer 2: 64 -> 128, 4x4 s2 p1, 128 -> 64 -------------
    {
        int Cin = 64, H = 128, W = 128, kh = 4, kw = 4, s = 2, p = 1;
        int Ho = 64, Wo = 64, K = 16, CK = 1024, HW = Ho * Wo;
        build_cols_plain<<<ceil_div(B * CK * HW, THREADS), THREADS>>>(
            h, col, B, Cin, H, W, kh, kw, s, p, Ho, Wo, CK, CK);
        gemm_f32x2<64><<<dim3(HW / BN, 1, B), 256>>>(w_off2, col, b_off2, om, 48, CK, HW);
        build_cols_deform<<<ceil_div(B * K * HW, THREADS), THREADS>>>(
            h, om, col, B, Cin, H, W, kh, kw, s, p, Ho, Wo, CK);
        gemm_f32x2<128><<<dim3(HW / BN, 1, B), 256>>>(w2, col, b2, pre, 128, CK, HW);
        instnorm<<<B * 128, THREADS>>>(pre, h, out + 4194304, nullptr, HW, 1);  // skip2
    }
    // ---------------- Layer 3: 128 -> 256, 4x4 s2 p1, 64 -> 32 -------------
    {
        int Cin = 128, H = 64, W = 64, kh = 4, kw = 4, s = 2, p = 1;
        int Ho = 32, Wo = 32, K = 16, CK = 2048, HW = Ho * Wo;
        build_cols_plain<<<ceil_div(B * CK * HW, THREADS), THREADS>>>(
            h, col, B, Cin, H, W, kh, kw, s, p, Ho, Wo, CK, CK);
        gemm_f32x2<64><<<dim3(HW / BN, 1, B), 256>>>(w_off3, col, b_off3, om, 48, CK, HW);
        build_cols_deform<<<ceil_div(B * K * HW, THREADS), THREADS>>>(
            h, om, col, B, Cin, H, W, kh, kw, s, p, Ho, Wo, CK);
        gemm_f32x2<128><<<dim3(HW / BN, 2, B), 256>>>(w3, col, b3, pre, 256, CK, HW);
        instnorm<<<B * 256, THREADS>>>(pre, h, out + 12582912, nullptr, HW, 1); // skip3
    }
    // ---------------- Residual blocks (256ch, 32x32) via im2col GEMM --------
    {
        const int HW = 1024, C = 256, CK = 2304;
        const float* wa[2]  = { rw0a, rw1a };
        const float* ba[2]  = { rb0a, rb1a };
        const float* wb[2]  = { rw0b, rw1b };
        const float* bbv[2] = { rb0b, rb1b };
        for (int r = 0; r < 2; r++) {
            build_cols_reflect<<<ceil_div(B * CK * HW, THREADS), THREADS>>>(h, col, B, C);
            gemm_f32x2<128><<<dim3(HW / BN, 2, B), 256>>>(wa[r], col, ba[r], pre, C, CK, HW);
            instnorm<<<B * C, THREADS>>>(pre, yb, nullptr, nullptr, HW, 1);
            build_cols_reflect<<<ceil_div(B * CK * HW, THREADS), THREADS>>>(yb, col, B, C);
            gemm_f32x2<128><<<dim3(HW / BN, 2, B), 256>>>(wb[r], col, bbv[r], pre, C, CK, HW);
            float* dst = (r == 0) ? h : out;   // final h goes straight to d_out
            instnorm<<<B * C, THREADS>>>(pre, dst, nullptr, h, HW, 0);
        }
    }
}

// round 5
// speedup vs baseline: 2.1191x; 1.1761x over previous
#include <cuda_runtime.h>
#include <math.h>

// ---------------------------------------------------------------------------
// Static scratch (no allocations allowed)
// ---------------------------------------------------------------------------
__device__ float g_col[67108864];   // im2col buffer (max 160*16*16384 = 41.9M)
__device__ float g_om [38535168];   // offset/mask maps (max 147*16*16384)
__device__ float g_h  [16777216];   // current activation
__device__ float g_pre[16777216];   // pre-IN conv output
__device__ float g_y  [ 4194304];   // residual branch
__device__ float g_wT [  589824];   // transposed weights (max 2304*256)

#define THREADS 256

// ---------------------------------------------------------------------------
// cp.async helpers
// ---------------------------------------------------------------------------
__device__ __forceinline__ void cpa16(void* s, const void* g) {
    unsigned sa = (unsigned)__cvta_generic_to_shared(s);
    asm volatile("cp.async.ca.shared.global [%0], [%1], 16;\n" :: "r"(sa), "l"(g));
}
__device__ __forceinline__ void cpa4(void* s, const void* g) {
    unsigned sa = (unsigned)__cvta_generic_to_shared(s);
    asm volatile("cp.async.ca.shared.global [%0], [%1], 4;\n" :: "r"(sa), "l"(g));
}
__device__ __forceinline__ void cp_commit() {
    asm volatile("cp.async.commit_group;");
}
template <int N>
__device__ __forceinline__ void cp_wait() {
    asm volatile("cp.async.wait_group %0;" :: "n"(N));
}

// ---------------------------------------------------------------------------
// Weight transpose + pad: dst[kidx][m] (Kp x Mp) from src[m][kidx] (M x K)
// ---------------------------------------------------------------------------
__global__ void transpose_pad(const float* __restrict__ src, float* __restrict__ dst,
                              int M, int K, int Mp, int Kp) {
    int t = blockIdx.x * THREADS + threadIdx.x;
    if (t >= Mp * Kp) return;
    int kidx = t / Mp, m = t % Mp;
    dst[t] = (kidx < K && m < M) ? src[m * K + kidx] : 0.f;
}

// Resblock weight transpose: dst[(k*256+ci)][m] = src[m][ci*9+k], 2304 x 256
__global__ void transpose_res(const float* __restrict__ src, float* __restrict__ dst) {
    int t = blockIdx.x * THREADS + threadIdx.x;
    if (t >= 2304 * 256) return;
    int kidx = t >> 8, m = t & 255;
    int k = kidx >> 8, ci = kidx & 255;
    dst[t] = src[m * 2304 + ci * 9 + k];
}

// ---------------------------------------------------------------------------
// Zero pad rows [CK, CKp) of col buffer, per batch
// ---------------------------------------------------------------------------
__global__ void zero_pad_rows(float* __restrict__ col, int B, int CK, int CKp, int HW) {
    int rows = CKp - CK;
    int t = blockIdx.x * THREADS + threadIdx.x;
    int total = B * rows * HW;
    if (t >= total) return;
    int pos = t % HW;
    int rest = t / HW;
    int r = rest % rows;
    int b = rest / rows;
    col[((size_t)b * CKp + CK + r) * HW + pos] = 0.f;
}

// ---------------------------------------------------------------------------
// Plain im2col (integer sampling, zero pad) : col[b][ci*K+k][pos], CKp stride
// ---------------------------------------------------------------------------
__global__ void build_cols_plain(const float* __restrict__ x, float* __restrict__ col,
                                 int B, int Cin, int H, int W,
                                 int kh, int kw, int stride, int pad,
                                 int Ho, int Wo, int CK, int CKp) {
    int K = kh * kw;
    int HW = Ho * Wo;
    int total = B * CKp * HW;
    int t = blockIdx.x * THREADS + threadIdx.x;
    if (t >= total) return;
    int pos = t % HW;
    int rest = t / HW;
    int ck = rest % CKp;
    int b  = rest / CKp;
    float v = 0.f;
    if (ck < CK) {
        int k  = ck % K;
        int ci = ck / K;
        int ho = pos / Wo, wo = pos % Wo;
        int iy = ho * stride - pad + (k / kw);
        int ix = wo * stride - pad + (k % kw);
        if (iy >= 0 && iy < H && ix >= 0 && ix < W)
            v = x[(((size_t)b * Cin + ci) * H + iy) * W + ix];
    }
    col[t] = v;
}

// ---------------------------------------------------------------------------
// Deformable im2col: bilinear sample at base+offset, times sigmoid(mask).
// Cin split into groups of CIG channels per thread for parallelism.
// ---------------------------------------------------------------------------
__global__ void build_cols_deform(const float* __restrict__ x, const float* __restrict__ om,
                                  float* __restrict__ col,
                                  int B, int Cin, int H, int W,
                                  int kh, int kw, int stride, int pad,
                                  int Ho, int Wo, int CKp, int CIG) {
    int K = kh * kw;
    int HW = Ho * Wo;
    int groups = Cin / CIG;
    int total = B * groups * K * HW;
    int t = blockIdx.x * THREADS + threadIdx.x;
    if (t >= total) return;
    int pos = t % HW;
    int rest = t / HW;
    int k = rest % K;  rest /= K;
    int g = rest % groups;
    int b = rest / groups;
    int ho = pos / Wo, wo = pos % Wo;

    const float* omb = om + (size_t)b * 3 * K * HW;
    float offy = omb[(size_t)(2 * k) * HW + pos];
    float offx = omb[(size_t)(2 * k + 1) * HW + pos];
    float mk   = omb[(size_t)(2 * K + k) * HW + pos];
    mk = 1.f / (1.f + expf(-mk));

    float yf = (float)(ho * stride - pad + k / kw) + offy;
    float xf = (float)(wo * stride - pad + k % kw) + offx;
    float y0f = floorf(yf), x0f = floorf(xf);
    float dy = yf - y0f, dx = xf - x0f;
    int y0 = (int)y0f, x0 = (int)x0f;
    int y1 = y0 + 1, x1 = x0 + 1;

    float w00 = (1.f - dy) * (1.f - dx) * mk;
    float w01 = (1.f - dy) * dx * mk;
    float w10 = dy * (1.f - dx) * mk;
    float w11 = dy * dx * mk;
    bool vy0 = (y0 >= 0) && (y0 < H);
    bool vy1 = (y1 >= 0) && (y1 < H);
    bool vx0 = (x0 >= 0) && (x0 < W);
    bool vx1 = (x1 >= 0) && (x1 < W);

    const float* xp = x + ((size_t)b * Cin + g * CIG) * H * W;
    float* cb = col + ((size_t)b * CKp + (size_t)(g * CIG) * K + k) * HW + pos;
    size_t plane = (size_t)H * W;
    size_t cstride = (size_t)K * HW;
    for (int c = 0; c < CIG; c++) {
        float v = 0.f;
        if (vy0 && vx0) v += w00 * xp[y0 * W + x0];
        if (vy0 && vx1) v += w01 * xp[y0 * W + x1];
        if (vy1 && vx0) v += w10 * xp[y1 * W + x0];
        if (vy1 && vx1) v += w11 * xp[y1 * W + x1];
        cb[(size_t)c * cstride] = v;
        xp += plane;
    }
}

// ---------------------------------------------------------------------------
// FFMA2 micro-kernel core: computes 16 kk steps from smem tiles.
// acc[RM][4] packed f32x2. tx in 0..15 (cols), ty in 0..15 (rows).
// ---------------------------------------------------------------------------
template <int BM>
__device__ __forceinline__ void mma_tile(const float (*As)[BM], const float (*Bs)[128],
                                         unsigned long long (*acc)[4], int tx, int ty) {
    constexpr int RM = BM / 16;
#pragma unroll
    for (int kk = 0; kk < 16; kk++) {
        double2 blo = *(const double2*)&Bs[kk][tx * 4];
        double2 bhi = *(const double2*)&Bs[kk][tx * 4 + 64];
        unsigned long long bp[4];
        bp[0] = __double_as_longlong(blo.x);
        bp[1] = __double_as_longlong(blo.y);
        bp[2] = __double_as_longlong(bhi.x);
        bp[3] = __double_as_longlong(bhi.y);

        float4 a0 = *(const float4*)&As[kk][ty * 4];
        float av[RM];
        av[0] = a0.x; av[1] = a0.y; av[2] = a0.z; av[3] = a0.w;
        if (BM == 128) {
            float4 a1 = *(const float4*)&As[kk][ty * 4 + 64];
            av[4] = a1.x; av[5] = a1.y; av[6] = a1.z; av[7] = a1.w;
        }
        unsigned long long ad[RM];
#pragma unroll
        for (int i = 0; i < RM; i++)
            asm("mov.b64 %0, {%1, %1};" : "=l"(ad[i]) : "f"(av[i]));
#pragma unroll
        for (int i = 0; i < RM; i++)
#pragma unroll
            for (int j = 0; j < 4; j++)
                asm("fma.rn.f32x2 %0, %1, %2, %0;"
                    : "+l"(acc[i][j]) : "l"(ad[i]), "l"(bp[j]));
    }
}

template <int BM>
__device__ __forceinline__ void epilogue(unsigned long long (*acc)[4],
                                         const float* bias, float* Cb,
                                         int M, int N, int tM, int tN, int tx, int ty) {
    constexpr int RM = BM / 16;
#pragma unroll
    for (int i = 0; i < RM; i++) {
        int gm = tM + ((i < 4) ? (ty * 4 + i) : (64 + ty * 4 + (i - 4)));
        if (gm >= M) continue;
        float bb = bias[gm];
        float o[8];
#pragma unroll
        for (int j = 0; j < 4; j++)
            asm("mov.b64 {%0, %1}, %2;"
                : "=f"(o[2 * j]), "=f"(o[2 * j + 1]) : "l"(acc[i][j]));
        float4 s0 = make_float4(o[0] + bb, o[1] + bb, o[2] + bb, o[3] + bb);
        float4 s1 = make_float4(o[4] + bb, o[5] + bb, o[6] + bb, o[7] + bb);
        *(float4*)&Cb[(size_t)gm * N + tN + tx * 4]      = s0;
        *(float4*)&Cb[(size_t)gm * N + tN + tx * 4 + 64] = s1;
    }
}

// ---------------------------------------------------------------------------
// GEMM v2: A pre-transposed (At[Kp][Mp]), cp.async 2-stage double buffer.
// C[b][m][n] = sum_k At[k][m] * Bcol[b][k][n] + bias[m]
// Requirements: Kp % 16 == 0, N % 128 == 0, Mp = gridDim.y * BM.
// ---------------------------------------------------------------------------
template <int BM>
__device__ __forceinline__ void load_tiles(const float* At, const float* Bb,
                                           float (*As)[BM], float (*Bs)[128],
                                           int k0, int tM, int tN, int Mp, int N, int tid) {
#pragma unroll
    for (int it = 0; it < BM / 64; it++) {
        int f4 = tid + it * 256;
        int kk = f4 / (BM / 4);
        int m4 = (f4 % (BM / 4)) * 4;
        cpa16(&As[kk][m4], &At[(size_t)(k0 + kk) * Mp + tM + m4]);
    }
#pragma unroll
    for (int it = 0; it < 2; it++) {
        int f4 = tid + it * 256;
        int kk = f4 >> 5, c4 = (f4 & 31) * 4;
        cpa16(&Bs[kk][c4], &Bb[(size_t)(k0 + kk) * N + tN + c4]);
    }
}

template <int BM>
__global__ void __launch_bounds__(256, 2)
gemm2(const float* __restrict__ At, const float* __restrict__ Bcol,
      const float* __restrict__ bias, float* __restrict__ C,
      int M, int Mp, int Kp, int N) {
    constexpr int RM = BM / 16;
    int b = blockIdx.z;
    const float* Bb = Bcol + (size_t)b * Kp * N;
    float* Cb = C + (size_t)b * M * N;
    int tM = blockIdx.y * BM;
    int tN = blockIdx.x * 128;

    __shared__ float As[2][16][BM];
    __shared__ float Bs[2][16][128];

    int tid = threadIdx.x;
    int tx = tid & 15;
    int ty = tid >> 4;

    unsigned long long acc[RM][4];
#pragma unroll
    for (int i = 0; i < RM; i++)
#pragma unroll
        for (int j = 0; j < 4; j++) acc[i][j] = 0ULL;

    int nt = Kp >> 4;
    load_tiles<BM>(At, Bb, As[0], Bs[0], 0, tM, tN, Mp, N, tid);
    cp_commit();
    for (int i = 0; i < nt; i++) {
        if (i + 1 < nt) {
            load_tiles<BM>(At, Bb, As[(i + 1) & 1], Bs[(i + 1) & 1],
                           (i + 1) << 4, tM, tN, Mp, N, tid);
            cp_commit();
            cp_wait<1>();
        } else {
            cp_wait<0>();
        }
        __syncthreads();
        mma_tile<BM>(As[i & 1], Bs[i & 1], acc, tx, ty);
        __syncthreads();
    }
    epilogue<BM>(acc, bias, Cb, M, N, tM, tN, tx, ty);
}

// ---------------------------------------------------------------------------
// Implicit-GEMM residual 3x3 reflect conv on 32x32 planes, Cin=Cout=256.
// K-dim ordered k*256+ci so each 16-row chunk has a single tap k.
// At[(k*256+ci)][co] pre-transposed. C written to pre buffer [b][co][1024].
// ---------------------------------------------------------------------------
__device__ __forceinline__ void load_tiles_res(const float* At, const float* xb,
                                               float (*As)[128], float (*Bs)[128],
                                               int k0, int tM, int tN, int tid) {
    // A tile: coalesced from At (Mp = 256)
#pragma unroll
    for (int it = 0; it < 2; it++) {
        int f4 = tid + it * 256;
        int kk = f4 >> 5;
        int m4 = (f4 & 31) * 4;
        cpa16(&As[kk][m4], &At[(size_t)(k0 + kk) * 256 + tM + m4]);
    }
    // B tile: reflect gather from activation
    int k = k0 >> 8;              // tap index, constant over chunk
    int ci0 = k0 & 255;
    int dy = k / 3 - 1, dx = k % 3 - 1;
#pragma unroll
    for (int it = 0; it < 2; it++) {
        int f4 = tid + it * 256;
        int row = f4 >> 5;        // ci offset within chunk
        int c4 = (f4 & 31) * 4;
        const float* xp = xb + ((size_t)(ci0 + row) << 10);
        int pos = tN + c4;
        int ho = pos >> 5, w0 = pos & 31;
        int iy = ho + dy;
        iy = iy < 0 ? -iy : (iy > 31 ? 62 - iy : iy);
        const float* xr = xp + iy * 32;
#pragma unroll
        for (int j = 0; j < 4; j++) {
            int wx = w0 + j + dx;
            wx = wx < 0 ? -wx : (wx > 31 ? 62 - wx : wx);
            cpa4(&Bs[row][c4 + j], &xr[wx]);
        }
    }
}

__global__ void __launch_bounds__(256, 2)
gemm_res(const float* __restrict__ At, const float* __restrict__ x,
         const float* __restrict__ bias, float* __restrict__ C) {
    int b = blockIdx.z;
    const float* xb = x + ((size_t)b << 18);         // b * 256 * 1024
    float* Cb = C + ((size_t)b << 18);
    int tM = blockIdx.y * 128;
    int tN = blockIdx.x * 128;

    __shared__ float As[2][16][128];
    __shared__ float Bs[2][16][128];

    int tid = threadIdx.x;
    int tx = tid & 15;
    int ty = tid >> 4;

    unsigned long long acc[8][4];
#pragma unroll
    for (int i = 0; i < 8; i++)
#pragma unroll
        for (int j = 0; j < 4; j++) acc[i][j] = 0ULL;

    const int nt = 2304 >> 4;  // 144
    load_tiles_res(At, xb, As[0], Bs[0], 0, tM, tN, tid);
    cp_commit();
    for (int i = 0; i < nt; i++) {
        if (i + 1 < nt) {
            load_tiles_res(At, xb, As[(i + 1) & 1], Bs[(i + 1) & 1],
                           (i + 1) << 4, tM, tN, tid);
            cp_commit();
            cp_wait<1>();
        } else {
            cp_wait<0>();
        }
        __syncthreads();
        mma_tile<128>(As[i & 1], Bs[i & 1], acc, tx, ty);
        __syncthreads();
    }
    epilogue<128>(acc, bias, Cb, 256, 1024, tM, tN, tx, ty);
}

// ---------------------------------------------------------------------------
// InstanceNorm over HW per (b,c) plane. Optional relu / residual add / 2nd dst.
// ---------------------------------------------------------------------------
__global__ void instnorm(const float* __restrict__ in, float* __restrict__ out,
                         float* __restrict__ out2, const float* __restrict__ addsrc,
                         int HW, int relu) {
    int plane = blockIdx.x;
    const float* p = in + (size_t)plane * HW;
    __shared__ float ssum[THREADS];
    __shared__ float ssq[THREADS];
    int tid = threadIdx.x;
    float s = 0.f, sq = 0.f;
    for (int i = tid; i < HW; i += THREADS) {
        float v = p[i];
        s += v; sq += v * v;
    }
    ssum[tid] = s; ssq[tid] = sq;
    __syncthreads();
    for (int off = THREADS / 2; off > 0; off >>= 1) {
        if (tid < off) { ssum[tid] += ssum[tid + off]; ssq[tid] += ssq[tid + off]; }
        __syncthreads();
    }
    __shared__ float mu_s, rs_s;
    if (tid == 0) {
        float mu = ssum[0] / (float)HW;
        float var = ssq[0] / (float)HW - mu * mu;
        mu_s = mu;
        rs_s = rsqrtf(var + 1e-5f);
    }
    __syncthreads();
    float mu = mu_s, rs = rs_s;
    float* o = out + (size_t)plane * HW;
    for (int i = tid; i < HW; i += THREADS) {
        float v = (p[i] - mu) * rs;
        if (relu) v = fmaxf(v, 0.f);
        if (addsrc) v += addsrc[(size_t)plane * HW + i];
        o[i] = v;
        if (out2) out2[(size_t)plane * HW + i] = v;
    }
}

// ---------------------------------------------------------------------------
// Host orchestration
// ---------------------------------------------------------------------------
static inline int ceil_div(int a, int b) { return (a + b - 1) / b; }

extern "C" void kernel_launch(void* const* d_in, const int* in_sizes, int n_in,
                              void* d_out, int out_size) {
    (void)in_sizes; (void)n_in; (void)out_size;
    const float* x      = (const float*)d_in[0];
    const float* w_off1 = (const float*)d_in[1];
    const float* b_off1 = (const float*)d_in[2];
    const float* w1     = (const float*)d_in[3];
    const float* b1     = (const float*)d_in[4];
    const float* w_off2 = (const float*)d_in[5];
    const float* b_off2 = (const float*)d_in[6];
    const float* w2     = (const float*)d_in[7];
    const float* b2     = (const float*)d_in[8];
    const float* w_off3 = (const float*)d_in[9];
    const float* b_off3 = (const float*)d_in[10];
    const float* w3     = (const float*)d_in[11];
    const float* b3     = (const float*)d_in[12];
    const float* rw0a   = (const float*)d_in[13];
    const float* rb0a   = (const float*)d_in[14];
    const float* rw0b   = (const float*)d_in[15];
    const float* rb0b   = (const float*)d_in[16];
    const float* rw1a   = (const float*)d_in[17];
    const float* rb1a   = (const float*)d_in[18];
    const float* rw1b   = (const float*)d_in[19];
    const float* rb1b   = (const float*)d_in[20];
    float* out = (float*)d_out;

    float *col, *om, *h, *pre, *yb, *wT;
    cudaGetSymbolAddress((void**)&col, g_col);
    cudaGetSymbolAddress((void**)&om,  g_om);
    cudaGetSymbolAddress((void**)&h,   g_h);
    cudaGetSymbolAddress((void**)&pre, g_pre);
    cudaGetSymbolAddress((void**)&yb,  g_y);
    cudaGetSymbolAddress((void**)&wT,  g_wT);

    const int B = 16;

    // ---------------- Layer 1: 3 -> 64, 7x7 s1 p3, 128x128 -> 128x128 ------
    {
        int Cin = 3, H = 128, W = 128, kh = 7, kw = 7, s = 1, p = 3;
        int Ho = 128, Wo = 128, K = 49, CK = 147, CKp = 160, HW = Ho * Wo;
        build_cols_plain<<<ceil_div(B * CKp * HW, THREADS), THREADS>>>(
            x, col, B, Cin, H, W, kh, kw, s, p, Ho, Wo, CK, CKp);
        transpose_pad<<<ceil_div(160 * 192, THREADS), THREADS>>>(w_off1, wT, 147, 147, 192, 160);
        gemm2<64><<<dim3(HW / 128, 3, B), 256>>>(wT, col, b_off1, om, 147, 192, CKp, HW);
        build_cols_deform<<<ceil_div(B * 1 * K * HW, THREADS), THREADS>>>(
            x, om, col, B, Cin, H, W, kh, kw, s, p, Ho, Wo, CKp, 3);
        zero_pad_rows<<<ceil_div(B * (CKp - CK) * HW, THREADS), THREADS>>>(col, B, CK, CKp, HW);
        transpose_pad<<<ceil_div(160 * 64, THREADS), THREADS>>>(w1, wT, 64, 147, 64, 160);
        gemm2<64><<<dim3(HW / 128, 1, B), 256>>>(wT, col, b1, pre, 64, 64, CKp, HW);
        instnorm<<<B * 64, THREADS>>>(pre, h, nullptr, nullptr, HW, 1);
    }
    // ---------------- Layer 2: 64 -> 128, 4x4 s2 p1, 128 -> 64 -------------
    {
        int Cin = 64, H = 128, W = 128, kh = 4, kw = 4, s = 2, p = 1;
        int Ho = 64, Wo = 64, K = 16, CK = 1024, HW = Ho * Wo;
        build_cols_plain<<<ceil_div(B * CK * HW, THREADS), THREADS>>>(
            h, col, B, Cin, H, W, kh, kw, s, p, Ho, Wo, CK, CK);
        transpose_pad<<<ceil_div(1024 * 64, THREADS), THREADS>>>(w_off2, wT, 48, 1024, 64, 1024);
        gemm2<64><<<dim3(HW / 128, 1, B), 256>>>(wT, col, b_off2, om, 48, 64, CK, HW);
        build_cols_deform<<<ceil_div(B * (Cin / 16) * K * HW, THREADS), THREADS>>>(
            h, om, col, B, Cin, H, W, kh, kw, s, p, Ho, Wo, CK, 16);
        transpose_pad<<<ceil_div(1024 * 128, THREADS), THREADS>>>(w2, wT, 128, 1024, 128, 1024);
        gemm2<128><<<dim3(HW / 128, 1, B), 256>>>(wT, col, b2, pre, 128, 128, CK, HW);
        instnorm<<<B * 128, THREADS>>>(pre, h, out + 4194304, nullptr, HW, 1);  // skip2
    }
    // ---------------- Layer 3: 128 -> 256, 4x4 s2 p1, 64 -> 32 -------------
    {
        int Cin = 128, H = 64, W = 64, kh = 4, kw = 4, s = 2, p = 1;
        int Ho = 32, Wo = 32, K = 16, CK = 2048, HW = Ho * Wo;
        build_cols_plain<<<ceil_div(B * CK * HW, THREADS), THREADS>>>(
            h, col, B, Cin, H, W, kh, kw, s, p, Ho, Wo, CK, CK);
        transpose_pad<<<ceil_div(2048 * 64, THREADS), THREADS>>>(w_off3, wT, 48, 2048, 64, 2048);
        gemm2<64><<<dim3(HW / 128, 1, B), 256>>>(wT, col, b_off3, om, 48, 64, CK, HW);
        build_cols_deform<<<ceil_div(B * (Cin / 16) * K * HW, THREADS), THREADS>>>(
            h, om, col, B, Cin, H, W, kh, kw, s, p, Ho, Wo, CK, 16);
        transpose_pad<<<ceil_div(2048 * 256, THREADS), THREADS>>>(w3, wT, 256, 2048, 256, 2048);
        gemm2<128><<<dim3(HW / 128, 2, B), 256>>>(wT, col, b3, pre, 256, 256, CK, HW);
        instnorm<<<B * 256, THREADS>>>(pre, h, out + 12582912, nullptr, HW, 1); // skip3
    }
    // ---------------- Residual blocks (256ch, 32x32), implicit GEMM ---------
    {
        const int HW = 1024, C = 256;
        const float* wa[2]  = { rw0a, rw1a };
        const float* ba[2]  = { rb0a, rb1a };
        const float* wb[2]  = { rw0b, rw1b };
        const float* bbv[2] = { rb0b, rb1b };
        for (int r = 0; r < 2; r++) {
            transpose_res<<<ceil_div(2304 * 256, THREADS), THREADS>>>(wa[r], wT);
            gemm_res<<<dim3(HW / 128, 2, B), 256>>>(wT, h, ba[r], pre);
            instnorm<<<B * C, THREADS>>>(pre, yb, nullptr, nullptr, HW, 1);
            transpose_res<<<ceil_div(2304 * 256, THREADS), THREADS>>>(wb[r], wT);
            gemm_res<<<dim3(HW / 128, 2, B), 256>>>(wT, yb, bbv[r], pre);
            float* dst = (r == 0) ? h : out;   // final h goes straight to d_out
            instnorm<<<B * C, THREADS>>>(pre, dst, nullptr, h, HW, 0);
        }
    }
}

// round 6
// speedup vs baseline: 2.5269x; 1.1925x over previous
#include <cuda_runtime.h>
#include <math.h>

// ---------------------------------------------------------------------------
// Static scratch (no allocations allowed)
// ---------------------------------------------------------------------------
__device__ float g_col[67108864];   // deform im2col buffer
__device__ float g_om [38535168];   // offset/mask maps (max 147*16*16384)
__device__ float g_h  [16777216];   // current activation
__device__ float g_pre[16777216];   // pre-IN conv output
__device__ float g_y  [ 4194304];   // residual branch
__device__ float g_wT [  589824];   // transposed weights (max 2304*256)

#define THREADS 256

// ---------------------------------------------------------------------------
// cp.async helpers
// ---------------------------------------------------------------------------
__device__ __forceinline__ void cpa16(void* s, const void* g) {
    unsigned sa = (unsigned)__cvta_generic_to_shared(s);
    asm volatile("cp.async.ca.shared.global [%0], [%1], 16;\n" :: "r"(sa), "l"(g));
}
__device__ __forceinline__ void cpa4(void* s, const void* g) {
    unsigned sa = (unsigned)__cvta_generic_to_shared(s);
    asm volatile("cp.async.ca.shared.global [%0], [%1], 4;\n" :: "r"(sa), "l"(g));
}
__device__ __forceinline__ void cp_commit() {
    asm volatile("cp.async.commit_group;");
}
template <int N>
__device__ __forceinline__ void cp_wait() {
    asm volatile("cp.async.wait_group %0;" :: "n"(N));
}

// ---------------------------------------------------------------------------
// Weight transpose + pad (ci*K+k ordering): dst[kidx][m] from src[m][kidx]
// ---------------------------------------------------------------------------
__global__ void transpose_pad(const float* __restrict__ src, float* __restrict__ dst,
                              int M, int K, int Mp, int Kp) {
    int t = blockIdx.x * THREADS + threadIdx.x;
    if (t >= Mp * Kp) return;
    int kidx = t / Mp, m = t % Mp;
    dst[t] = (kidx < K && m < M) ? src[m * K + kidx] : 0.f;
}

// Offset-conv weight transpose (tap-major): dst[(k*Cin+ci)][m] = src[m][ci*K+k]
__global__ void transpose_off(const float* __restrict__ src, float* __restrict__ dst,
                              int M, int Cin, int K, int Mp, int Kp) {
    int t = blockIdx.x * THREADS + threadIdx.x;
    if (t >= Mp * Kp) return;
    int kidx = t / Mp, m = t % Mp;
    float v = 0.f;
    if (kidx < Cin * K && m < M) {
        int k = kidx / Cin, ci = kidx - k * Cin;
        v = src[m * Cin * K + ci * K + k];
    }
    dst[t] = v;
}

// Resblock weight transpose: dst[(k*256+ci)][m] = src[m][ci*9+k], 2304 x 256
__global__ void transpose_res(const float* __restrict__ src, float* __restrict__ dst) {
    int t = blockIdx.x * THREADS + threadIdx.x;
    if (t >= 2304 * 256) return;
    int kidx = t >> 8, m = t & 255;
    int k = kidx >> 8, ci = kidx & 255;
    dst[t] = src[m * 2304 + ci * 9 + k];
}

// ---------------------------------------------------------------------------
// Zero pad rows [CK, CKp) of col buffer, per batch
// ---------------------------------------------------------------------------
__global__ void zero_pad_rows(float* __restrict__ col, int B, int CK, int CKp, int HW) {
    int rows = CKp - CK;
    int t = blockIdx.x * THREADS + threadIdx.x;
    int total = B * rows * HW;
    if (t >= total) return;
    int pos = t % HW;
    int rest = t / HW;
    int r = rest % rows;
    int b = rest / rows;
    col[((size_t)b * CKp + CK + r) * HW + pos] = 0.f;
}

// ---------------------------------------------------------------------------
// Templated deform im2col: 4 positions per thread, branchless bilinear
// (clamped indices, zeroed weights), compile-time geometry.
// om layout [B][3K][HW]; col[b][(g*CIG+c)*K+k][pos], CKp row stride per batch.
// ---------------------------------------------------------------------------
template <int Cin, int CIG, int K, int KW, int S, int P, int Hd, int Wd, int Wo, int HW>
__global__ void build_deform_t(const float* __restrict__ x, const float* __restrict__ om,
                               float* __restrict__ col, int CKp) {
    constexpr int G = Cin / CIG;
    constexpr int Q = HW / 4;
    int t = blockIdx.x * THREADS + threadIdx.x;
    if (t >= 16 * G * K * Q) return;
    int q = t % Q;  int rest = t / Q;
    int k = rest % K; rest /= K;
    int g = rest % G;
    int b = rest / G;

    int pos = q * 4;
    int ho = pos / Wo;          // Wo is a power of two -> shift
    int wo = pos % Wo;

    const float* omb = om + (size_t)b * 3 * K * HW;
    float4 oy = *(const float4*)&omb[(size_t)(2 * k) * HW + pos];
    float4 ox = *(const float4*)&omb[(size_t)(2 * k + 1) * HW + pos];
    float4 mv = *(const float4*)&omb[(size_t)(2 * K + k) * HW + pos];
    float oyv[4] = {oy.x, oy.y, oy.z, oy.w};
    float oxv[4] = {ox.x, ox.y, ox.z, ox.w};
    float mkv[4] = {mv.x, mv.y, mv.z, mv.w};

    int ky = k / KW, kx = k - ky * KW;
    float by = (float)(ho * S - P + ky);

    float wgt[4][4];
    int   idx[4][4];
#pragma unroll
    for (int j = 0; j < 4; j++) {
        float mk = 1.f / (1.f + expf(-mkv[j]));
        float yf = by + oyv[j];
        float xf = (float)((wo + j) * S - P + kx) + oxv[j];
        float y0f = floorf(yf), x0f = floorf(xf);
        float dy = yf - y0f, dx = xf - x0f;
        int y0 = (int)y0f, x0 = (int)x0f;
        int y1 = y0 + 1, x1 = x0 + 1;
        bool vy0 = (y0 >= 0) & (y0 < Hd);
        bool vy1 = (y1 >= 0) & (y1 < Hd);
        bool vx0 = (x0 >= 0) & (x0 < Wd);
        bool vx1 = (x1 >= 0) & (x1 < Wd);
        float w00 = (1.f - dy) * (1.f - dx) * mk;
        float w01 = (1.f - dy) * dx * mk;
        float w10 = dy * (1.f - dx) * mk;
        float w11 = dy * dx * mk;
        wgt[j][0] = (vy0 & vx0) ? w00 : 0.f;
        wgt[j][1] = (vy0 & vx1) ? w01 : 0.f;
        wgt[j][2] = (vy1 & vx0) ? w10 : 0.f;
        wgt[j][3] = (vy1 & vx1) ? w11 : 0.f;
        int y0c = min(max(y0, 0), Hd - 1);
        int y1c = min(max(y1, 0), Hd - 1);
        int x0c = min(max(x0, 0), Wd - 1);
        int x1c = min(max(x1, 0), Wd - 1);
        idx[j][0] = y0c * Wd + x0c;
        idx[j][1] = y0c * Wd + x1c;
        idx[j][2] = y1c * Wd + x0c;
        idx[j][3] = y1c * Wd + x1c;
    }

    const float* xp = x + ((size_t)b * Cin + g * CIG) * (Hd * Wd);
    float* cb = col + ((size_t)b * CKp + (size_t)(g * CIG) * K + k) * HW + pos;
#pragma unroll 2
    for (int c = 0; c < CIG; c++) {
        float4 v;
        v.x = wgt[0][0] * xp[idx[0][0]] + wgt[0][1] * xp[idx[0][1]]
            + wgt[0][2] * xp[idx[0][2]] + wgt[0][3] * xp[idx[0][3]];
        v.y = wgt[1][0] * xp[idx[1][0]] + wgt[1][1] * xp[idx[1][1]]
            + wgt[1][2] * xp[idx[1][2]] + wgt[1][3] * xp[idx[1][3]];
        v.z = wgt[2][0] * xp[idx[2][0]] + wgt[2][1] * xp[idx[2][1]]
            + wgt[2][2] * xp[idx[2][2]] + wgt[2][3] * xp[idx[2][3]];
        v.w = wgt[3][0] * xp[idx[3][0]] + wgt[3][1] * xp[idx[3][1]]
            + wgt[3][2] * xp[idx[3][2]] + wgt[3][3] * xp[idx[3][3]];
        *(float4*)cb = v;
        xp += Hd * Wd;
        cb += (size_t)K * HW;
    }
}

// ---------------------------------------------------------------------------
// FFMA2 micro-kernel core + epilogue (shared by all GEMMs)
// ---------------------------------------------------------------------------
template <int BM>
__device__ __forceinline__ void mma_tile(const float (*As)[BM], const float (*Bs)[128],
                                         unsigned long long (*acc)[4], int tx, int ty) {
    constexpr int RM = BM / 16;
#pragma unroll
    for (int kk = 0; kk < 16; kk++) {
        double2 blo = *(const double2*)&Bs[kk][tx * 4];
        double2 bhi = *(const double2*)&Bs[kk][tx * 4 + 64];
        unsigned long long bp[4];
        bp[0] = __double_as_longlong(blo.x);
        bp[1] = __double_as_longlong(blo.y);
        bp[2] = __double_as_longlong(bhi.x);
        bp[3] = __double_as_longlong(bhi.y);

        float4 a0 = *(const float4*)&As[kk][ty * 4];
        float av[RM];
        av[0] = a0.x; av[1] = a0.y; av[2] = a0.z; av[3] = a0.w;
        if (BM == 128) {
            float4 a1 = *(const float4*)&As[kk][ty * 4 + 64];
            av[4] = a1.x; av[5] = a1.y; av[6] = a1.z; av[7] = a1.w;
        }
        unsigned long long ad[RM];
#pragma unroll
        for (int i = 0; i < RM; i++)
            asm("mov.b64 %0, {%1, %1};" : "=l"(ad[i]) : "f"(av[i]));
#pragma unroll
        for (int i = 0; i < RM; i++)
#pragma unroll
            for (int j = 0; j < 4; j++)
                asm("fma.rn.f32x2 %0, %1, %2, %0;"
                    : "+l"(acc[i][j]) : "l"(ad[i]), "l"(bp[j]));
    }
}

template <int BM>
__device__ __forceinline__ void epilogue(unsigned long long (*acc)[4],
                                         const float* bias, float* Cb,
                                         int M, int N, int tM, int tN, int tx, int ty) {
    constexpr int RM = BM / 16;
#pragma unroll
    for (int i = 0; i < RM; i++) {
        int gm = tM + ((i < 4) ? (ty * 4 + i) : (64 + ty * 4 + (i - 4)));
        if (gm >= M) continue;
        float bb = bias[gm];
        float o[8];
#pragma unroll
        for (int j = 0; j < 4; j++)
            asm("mov.b64 {%0, %1}, %2;"
                : "=f"(o[2 * j]), "=f"(o[2 * j + 1]) : "l"(acc[i][j]));
        float4 s0 = make_float4(o[0] + bb, o[1] + bb, o[2] + bb, o[3] + bb);
        float4 s1 = make_float4(o[4] + bb, o[5] + bb, o[6] + bb, o[7] + bb);
        *(float4*)&Cb[(size_t)gm * N + tN + tx * 4]      = s0;
        *(float4*)&Cb[(size_t)gm * N + tN + tx * 4 + 64] = s1;
    }
}

// ---------------------------------------------------------------------------
// GEMM v2 (col-consuming): A pre-transposed, cp.async double buffer.
// ---------------------------------------------------------------------------
template <int BM>
__device__ __forceinline__ void load_tiles(const float* At, const float* Bb,
                                           float (*As)[BM], float (*Bs)[128],
                                           int k0, int tM, int tN, int Mp, int N, int tid) {
#pragma unroll
    for (int it = 0; it < BM / 64; it++) {
        int f4 = tid + it * 256;
        int kk = f4 / (BM / 4);
        int m4 = (f4 % (BM / 4)) * 4;
        cpa16(&As[kk][m4], &At[(size_t)(k0 + kk) * Mp + tM + m4]);
    }
#pragma unroll
    for (int it = 0; it < 2; it++) {
        int f4 = tid + it * 256;
        int kk = f4 >> 5, c4 = (f4 & 31) * 4;
        cpa16(&Bs[kk][c4], &Bb[(size_t)(k0 + kk) * N + tN + c4]);
    }
}

template <int BM>
__global__ void __launch_bounds__(256, 2)
gemm2(const float* __restrict__ At, const float* __restrict__ Bcol,
      const float* __restrict__ bias, float* __restrict__ C,
      int M, int Mp, int Kp, int N) {
    constexpr int RM = BM / 16;
    int b = blockIdx.z;
    const float* Bb = Bcol + (size_t)b * Kp * N;
    float* Cb = C + (size_t)b * M * N;
    int tM = blockIdx.y * BM;
    int tN = blockIdx.x * 128;

    __shared__ float As[2][16][BM];
    __shared__ float Bs[2][16][128];

    int tid = threadIdx.x;
    int tx = tid & 15;
    int ty = tid >> 4;

    unsigned long long acc[RM][4];
#pragma unroll
    for (int i = 0; i < RM; i++)
#pragma unroll
        for (int j = 0; j < 4; j++) acc[i][j] = 0ULL;

    int nt = Kp >> 4;
    load_tiles<BM>(At, Bb, As[0], Bs[0], 0, tM, tN, Mp, N, tid);
    cp_commit();
    for (int i = 0; i < nt; i++) {
        if (i + 1 < nt) {
            load_tiles<BM>(At, Bb, As[(i + 1) & 1], Bs[(i + 1) & 1],
                           (i + 1) << 4, tM, tN, Mp, N, tid);
            cp_commit();
            cp_wait<1>();
        } else {
            cp_wait<0>();
        }
        __syncthreads();
        mma_tile<BM>(As[i & 1], Bs[i & 1], acc, tx, ty);
        __syncthreads();
    }
    epilogue<BM>(acc, bias, Cb, M, N, tM, tN, tx, ty);
}

// ---------------------------------------------------------------------------
// Implicit-GEMM offset conv: B-tile gathered straight from activation,
// zero-padded borders, compile-time conv geometry. K-dim order k*Cin+ci
// (matches transpose_off). C[b][m][pos] = conv + bias.
// ---------------------------------------------------------------------------
template <int BM, int Cin, int KH, int KW, int S, int P, int Hd, int Wd, int WoL2>
__global__ void __launch_bounds__(256, 2)
gemm_off(const float* __restrict__ At, const float* __restrict__ x,
         const float* __restrict__ bias, float* __restrict__ C,
         int M, int Mp, int Kp, int N) {
    constexpr int RM = BM / 16;
    constexpr int CK = Cin * KH * KW;
    int b = blockIdx.z;
    const float* xb = x + (size_t)b * Cin * Hd * Wd;
    float* Cb = C + (size_t)b * M * N;
    int tM = blockIdx.y * BM;
    int tN = blockIdx.x * 128;

    __shared__ float As[2][16][BM];
    __shared__ float Bs[2][16][128];

    int tid = threadIdx.x;
    int tx = tid & 15;
    int ty = tid >> 4;

    auto load = [&](float (*As_)[BM], float (*Bs_)[128], int k0) {
#pragma unroll
        for (int it = 0; it < BM / 64; it++) {
            int f4 = tid + it * 256;
            int kk = f4 / (BM / 4);
            int m4 = (f4 % (BM / 4)) * 4;
            cpa16(&As_[kk][m4], &At[(size_t)(k0 + kk) * Mp + tM + m4]);
        }
#pragma unroll
        for (int it = 0; it < 2; it++) {
            int f4 = tid + it * 256;
            int row = f4 >> 5;
            int c4 = (f4 & 31) * 4;
            int kidx = k0 + row;
            int pos = tN + c4;
            int ho = pos >> WoL2;
            int wo = pos & ((1 << WoL2) - 1);
            if (kidx < CK) {
                int k = kidx / Cin, ci = kidx - (kidx / Cin) * Cin;
                int ky = k / KW, kx = k - ky * KW;
                int iy = ho * S - P + ky;
                bool yok = (iy >= 0) & (iy < Hd);
                const float* xr = xb + (size_t)ci * Hd * Wd + (size_t)iy * Wd;
#pragma unroll
                for (int j = 0; j < 4; j++) {
                    int ix = (wo + j) * S - P + kx;
                    if (yok && ix >= 0 && ix < Wd) cpa4(&Bs_[row][c4 + j], &xr[ix]);
                    else Bs_[row][c4 + j] = 0.f;
                }
            } else {
                *(float4*)&Bs_[row][c4] = make_float4(0.f, 0.f, 0.f, 0.f);
            }
        }
    };

    unsigned long long acc[RM][4];
#pragma unroll
    for (int i = 0; i < RM; i++)
#pragma unroll
        for (int j = 0; j < 4; j++) acc[i][j] = 0ULL;

    int nt = Kp >> 4;
    load(As[0], Bs[0], 0);
    cp_commit();
    for (int i = 0; i < nt; i++) {
        if (i + 1 < nt) {
            load(As[(i + 1) & 1], Bs[(i + 1) & 1], (i + 1) << 4);
            cp_commit();
            cp_wait<1>();
        } else {
            cp_wait<0>();
        }
        __syncthreads();
        mma_tile<BM>(As[i & 1], Bs[i & 1], acc, tx, ty);
        __syncthreads();
    }
    epilogue<BM>(acc, bias, Cb, M, N, tM, tN, tx, ty);
}

// ---------------------------------------------------------------------------
// Implicit-GEMM residual 3x3 reflect conv on 32x32 planes, Cin=Cout=256.
// ---------------------------------------------------------------------------
__device__ __forceinline__ void load_tiles_res(const float* At, const float* xb,
                                               float (*As)[128], float (*Bs)[128],
                                               int k0, int tM, int tN, int tid) {
#pragma unroll
    for (int it = 0; it < 2; it++) {
        int f4 = tid + it * 256;
        int kk = f4 >> 5;
        int m4 = (f4 & 31) * 4;
        cpa16(&As[kk][m4], &At[(size_t)(k0 + kk) * 256 + tM + m4]);
    }
    int k = k0 >> 8;
    int ci0 = k0 & 255;
    int dy = k / 3 - 1, dx = k % 3 - 1;
#pragma unroll
    for (int it = 0; it < 2; it++) {
        int f4 = tid + it * 256;
        int row = f4 >> 5;
        int c4 = (f4 & 31) * 4;
        const float* xp = xb + ((size_t)(ci0 + row) << 10);
        int pos = tN + c4;
        int ho = pos >> 5, w0 = pos & 31;
        int iy = ho + dy;
        iy = iy < 0 ? -iy : (iy > 31 ? 62 - iy : iy);
        const float* xr = xp + iy * 32;
#pragma unroll
        for (int j = 0; j < 4; j++) {
            int wx = w0 + j + dx;
            wx = wx < 0 ? -wx : (wx > 31 ? 62 - wx : wx);
            cpa4(&Bs[row][c4 + j], &xr[wx]);
        }
    }
}

__global__ void __launch_bounds__(256, 2)
gemm_res(const float* __restrict__ At, const float* __restrict__ x,
         const float* __restrict__ bias, float* __restrict__ C) {
    int b = blockIdx.z;
    const float* xb = x + ((size_t)b << 18);
    float* Cb = C + ((size_t)b << 18);
    int tM = blockIdx.y * 128;
    int tN = blockIdx.x * 128;

    __shared__ float As[2][16][128];
    __shared__ float Bs[2][16][128];

    int tid = threadIdx.x;
    int tx = tid & 15;
    int ty = tid >> 4;

    unsigned long long acc[8][4];
#pragma unroll
    for (int i = 0; i < 8; i++)
#pragma unroll
        for (int j = 0; j < 4; j++) acc[i][j] = 0ULL;

    const int nt = 2304 >> 4;
    load_tiles_res(At, xb, As[0], Bs[0], 0, tM, tN, tid);
    cp_commit();
    for (int i = 0; i < nt; i++) {
        if (i + 1 < nt) {
            load_tiles_res(At, xb, As[(i + 1) & 1], Bs[(i + 1) & 1],
                           (i + 1) << 4, tM, tN, tid);
            cp_commit();
            cp_wait<1>();
        } else {
            cp_wait<0>();
        }
        __syncthreads();
        mma_tile<128>(As[i & 1], Bs[i & 1], acc, tx, ty);
        __syncthreads();
    }
    epilogue<128>(acc, bias, Cb, 256, 1024, tM, tN, tx, ty);
}

// ---------------------------------------------------------------------------
// InstanceNorm over HW per (b,c) plane. Optional relu / residual add / 2nd dst.
// ---------------------------------------------------------------------------
__global__ void instnorm(const float* __restrict__ in, float* __restrict__ out,
                         float* __restrict__ out2, const float* __restrict__ addsrc,
                         int HW, int relu) {
    int plane = blockIdx.x;
    const float* p = in + (size_t)plane * HW;
    __shared__ float ssum[THREADS];
    __shared__ float ssq[THREADS];
    int tid = threadIdx.x;
    float s = 0.f, sq = 0.f;
    for (int i = tid; i < HW; i += THREADS) {
        float v = p[i];
        s += v; sq += v * v;
    }
    ssum[tid] = s; ssq[tid] = sq;
    __syncthreads();
    for (int off = THREADS / 2; off > 0; off >>= 1) {
        if (tid < off) { ssum[tid] += ssum[tid + off]; ssq[tid] += ssq[tid + off]; }
        __syncthreads();
    }
    __shared__ float mu_s, rs_s;
    if (tid == 0) {
        float mu = ssum[0] / (float)HW;
        float var = ssq[0] / (float)HW - mu * mu;
        mu_s = mu;
        rs_s = rsqrtf(var + 1e-5f);
    }
    __syncthreads();
    float mu = mu_s, rs = rs_s;
    float* o = out + (size_t)plane * HW;
    for (int i = tid; i < HW; i += THREADS) {
        float v = (p[i] - mu) * rs;
        if (relu) v = fmaxf(v, 0.f);
        if (addsrc) v += addsrc[(size_t)plane * HW + i];
        o[i] = v;
        if (out2) out2[(size_t)plane * HW + i] = v;
    }
}

// ---------------------------------------------------------------------------
// Host orchestration
// ---------------------------------------------------------------------------
static inline int ceil_div(int a, int b) { return (a + b - 1) / b; }

extern "C" void kernel_launch(void* const* d_in, const int* in_sizes, int n_in,
                              void* d_out, int out_size) {
    (void)in_sizes; (void)n_in; (void)out_size;
    const float* x      = (const float*)d_in[0];
    const float* w_off1 = (const float*)d_in[1];
    const float* b_off1 = (const float*)d_in[2];
    const float* w1     = (const float*)d_in[3];
    const float* b1     = (const float*)d_in[4];
    const float* w_off2 = (const float*)d_in[5];
    const float* b_off2 = (const float*)d_in[6];
    const float* w2     = (const float*)d_in[7];
    const float* b2     = (const float*)d_in[8];
    const float* w_off3 = (const float*)d_in[9];
    const float* b_off3 = (const float*)d_in[10];
    const float* w3     = (const float*)d_in[11];
    const float* b3     = (const float*)d_in[12];
    const float* rw0a   = (const float*)d_in[13];
    const float* rb0a   = (const float*)d_in[14];
    const float* rw0b   = (const float*)d_in[15];
    const float* rb0b   = (const float*)d_in[16];
    const float* rw1a   = (const float*)d_in[17];
    const float* rb1a   = (const float*)d_in[18];
    const float* rw1b   = (const float*)d_in[19];
    const float* rb1b   = (const float*)d_in[20];
    float* out = (float*)d_out;

    float *col, *om, *h, *pre, *yb, *wT;
    cudaGetSymbolAddress((void**)&col, g_col);
    cudaGetSymbolAddress((void**)&om,  g_om);
    cudaGetSymbolAddress((void**)&h,   g_h);
    cudaGetSymbolAddress((void**)&pre, g_pre);
    cudaGetSymbolAddress((void**)&yb,  g_y);
    cudaGetSymbolAddress((void**)&wT,  g_wT);

    const int B = 16;

    // ---------------- Layer 1: 3 -> 64, 7x7 s1 p3, 128x128 -> 128x128 ------
    {
        const int HW = 16384, CK = 147, CKp = 160;
        transpose_off<<<ceil_div(160 * 192, THREADS), THREADS>>>(w_off1, wT, 147, 3, 49, 192, 160);
        gemm_off<64, 3, 7, 7, 1, 3, 128, 128, 7><<<dim3(HW / 128, 3, B), 256>>>(
            wT, x, b_off1, om, 147, 192, 160, HW);
        build_deform_t<3, 3, 49, 7, 1, 3, 128, 128, 128, 16384>
            <<<ceil_div(B * 49 * (HW / 4), THREADS), THREADS>>>(x, om, col, CKp);
        zero_pad_rows<<<ceil_div(B * (CKp - CK) * HW, THREADS), THREADS>>>(col, B, CK, CKp, HW);
        transpose_pad<<<ceil_div(160 * 64, THREADS), THREADS>>>(w1, wT, 64, 147, 64, 160);
        gemm2<64><<<dim3(HW / 128, 1, B), 256>>>(wT, col, b1, pre, 64, 64, CKp, HW);
        instnorm<<<B * 64, THREADS>>>(pre, h, nullptr, nullptr, HW, 1);
    }
    // ---------------- Layer 2: 64 -> 128, 4x4 s2 p1, 128 -> 64 -------------
    {
        const int HW = 4096, CK = 1024;
        transpose_off<<<ceil_div(1024 * 64, THREADS), THREADS>>>(w_off2, wT, 48, 64, 16, 64, 1024);
        gemm_off<64, 64, 4, 4, 2, 1, 128, 128, 6><<<dim3(HW / 128, 1, B), 256>>>(
            wT, h, b_off2, om, 48, 64, 1024, HW);
        build_deform_t<64, 16, 16, 4, 2, 1, 128, 128, 64, 4096>
            <<<ceil_div(B * 4 * 16 * (HW / 4), THREADS), THREADS>>>(h, om, col, CK);
        transpose_pad<<<ceil_div(1024 * 128, THREADS), THREADS>>>(w2, wT, 128, 1024, 128, 1024);
        gemm2<128><<<dim3(HW / 128, 1, B), 256>>>(wT, col, b2, pre, 128, 128, CK, HW);
        instnorm<<<B * 128, THREADS>>>(pre, h, out + 4194304, nullptr, HW, 1);  // skip2
    }
    // ---------------- Layer 3: 128 -> 256, 4x4 s2 p1, 64 -> 32 -------------
    {
        const int HW = 1024, CK = 2048;
        transpose_off<<<ceil_div(2048 * 64, THREADS), THREADS>>>(w_off3, wT, 48, 128, 16, 64, 2048);
        gemm_off<64, 128, 4, 4, 2, 1, 64, 64, 5><<<dim3(HW / 128, 1, B), 256>>>(
            wT, h, b_off3, om, 48, 64, 2048, HW);
        build_deform_t<128, 16, 16, 4, 2, 1, 64, 64, 32, 1024>
            <<<ceil_div(B * 8 * 16 * (HW / 4), THREADS), THREADS>>>(h, om, col, CK);
        transpose_pad<<<ceil_div(2048 * 256, THREADS), THREADS>>>(w3, wT, 256, 2048, 256, 2048);
        gemm2<128><<<dim3(HW / 128, 2, B), 256>>>(wT, col, b3, pre, 256, 256, CK, HW);
        instnorm<<<B * 256, THREADS>>>(pre, h, out + 12582912, nullptr, HW, 1); // skip3
    }
    // ---------------- Residual blocks (256ch, 32x32), implicit GEMM ---------
    {
        const int HW = 1024, C = 256;
        const float* wa[2]  = { rw0a, rw1a };
        const float* ba[2]  = { rb0a, rb1a };
        const float* wb[2]  = { rw0b, rw1b };
        const float* bbv[2] = { rb0b, rb1b };
        for (int r = 0; r < 2; r++) {
            transpose_res<<<ceil_div(2304 * 256, THREADS), THREADS>>>(wa[r], wT);
            gemm_res<<<dim3(HW / 128, 2, B), 256>>>(wT, h, ba[r], pre);
            instnorm<<<B * C, THREADS>>>(pre, yb, nullptr, nullptr, HW, 1);
            transpose_res<<<ceil_div(2304 * 256, THREADS), THREADS>>>(wb[r], wT);
            gemm_res<<<dim3(HW / 128, 2, B), 256>>>(wT, yb, bbv[r], pre);
            float* dst = (r == 0) ? h : out;   // final h goes straight to d_out
            instnorm<<<B * C, THREADS>>>(pre, dst, nullptr, h, HW, 0);
        }
    }
}

// round 8
// speedup vs baseline: 3.1633x; 1.2518x over previous
#include <cuda_runtime.h>
#include <cuda_bf16.h>
#include <math.h>

// ---------------------------------------------------------------------------
// Static scratch (no allocations allowed)
// ---------------------------------------------------------------------------
__device__ float g_col[67108864];   // deform im2col buffer
__device__ float g_om [38535168];   // offset/mask maps
__device__ float g_h  [16777216];   // current activation
__device__ float g_pre[16777216];   // pre-IN conv output
__device__ float g_y  [ 4194304];   // residual branch
__device__ float g_wT [  589824];   // transposed weights (fp32 path)
__device__ __align__(16) unsigned short g_xh[4194304];  // bf16-hi activation, pos-major
__device__ __align__(16) unsigned short g_xl[4194304];  // bf16-lo
__device__ uint4 g_wfrag[147456];                       // fragment-ordered bf16 weights

#define THREADS 256

// ---------------------------------------------------------------------------
// cp.async helpers
// ---------------------------------------------------------------------------
__device__ __forceinline__ void cpa16(void* s, const void* g) {
    unsigned sa = (unsigned)__cvta_generic_to_shared(s);
    asm volatile("cp.async.ca.shared.global [%0], [%1], 16;\n" :: "r"(sa), "l"(g));
}
__device__ __forceinline__ void cpa16_s(unsigned sa, const void* g) {
    asm volatile("cp.async.ca.shared.global [%0], [%1], 16;\n" :: "r"(sa), "l"(g));
}
__device__ __forceinline__ void cpa4(void* s, const void* g) {
    unsigned sa = (unsigned)__cvta_generic_to_shared(s);
    asm volatile("cp.async.ca.shared.global [%0], [%1], 4;\n" :: "r"(sa), "l"(g));
}
__device__ __forceinline__ void cp_commit() {
    asm volatile("cp.async.commit_group;");
}
template <int N>
__device__ __forceinline__ void cp_wait() {
    asm volatile("cp.async.wait_group %0;" :: "n"(N));
}

// ---------------------------------------------------------------------------
// Weight transposes (fp32 path, unchanged)
// ---------------------------------------------------------------------------
__global__ void transpose_pad(const float* __restrict__ src, float* __restrict__ dst,
                              int M, int K, int Mp, int Kp) {
    int t = blockIdx.x * THREADS + threadIdx.x;
    if (t >= Mp * Kp) return;
    int kidx = t / Mp, m = t % Mp;
    dst[t] = (kidx < K && m < M) ? src[m * K + kidx] : 0.f;
}

__global__ void transpose_off(const float* __restrict__ src, float* __restrict__ dst,
                              int M, int Cin, int K, int Mp, int Kp) {
    int t = blockIdx.x * THREADS + threadIdx.x;
    if (t >= Mp * Kp) return;
    int kidx = t / Mp, m = t % Mp;
    float v = 0.f;
    if (kidx < Cin * K && m < M) {
        int k = kidx / Cin, ci = kidx - k * Cin;
        v = src[m * Cin * K + ci * K + k];
    }
    dst[t] = v;
}

// ---------------------------------------------------------------------------
// Resblock weights -> mma.sync fragment order, bf16 hi/lo.
// frag[hl*73728 + (mg*144 + c)*32 + lane] = {a0,a1,a2,a3} for m16n8k16.
// mg = 16-row tile (0..15), c = chunk (tap = c>>4, ci0 = (c&15)*16).
// a0=(r0,k0,k0+1) a1=(r0+8,k0) a2=(r0,k0+8) a3=(r0+8,k0+8); r0=mg*16+g, k0=ci0+q*2.
// ---------------------------------------------------------------------------
__global__ void w_split_frag(const float* __restrict__ w, uint4* __restrict__ frag) {
    int t = blockIdx.x * THREADS + threadIdx.x;
    if (t >= 147456) return;
    int lane = t & 31;
    int rest = t >> 5;
    int c = rest % 144; rest /= 144;
    int mg = rest & 15;
    int hl = rest >> 4;
    int g = lane >> 2, q = lane & 3;
    int tap = c >> 4, ci0 = (c & 15) << 4;
    int r0 = (mg << 4) + g;
    int k0 = ci0 + (q << 1);
    unsigned rr[4];
#pragma unroll
    for (int e = 0; e < 4; e++) {
        int r = r0 + ((e & 1) << 3);
        int kk = k0 + ((e >> 1) << 3);
        float v0 = w[(size_t)r * 2304 + kk * 9 + tap];
        float v1 = w[(size_t)r * 2304 + (kk + 1) * 9 + tap];
        unsigned short u0, u1;
        if (hl == 0) {
            u0 = __bfloat16_as_ushort(__float2bfloat16(v0));
            u1 = __bfloat16_as_ushort(__float2bfloat16(v1));
        } else {
            __nv_bfloat16 h0 = __float2bfloat16(v0);
            __nv_bfloat16 h1 = __float2bfloat16(v1);
            u0 = __bfloat16_as_ushort(__float2bfloat16(v0 - __bfloat162float(h0)));
            u1 = __bfloat16_as_ushort(__float2bfloat16(v1 - __bfloat162float(h1)));
        }
        rr[e] = (unsigned)u0 | ((unsigned)u1 << 16);
    }
    frag[(size_t)hl * 73728 + ((size_t)mg * 144 + c) * 32 + lane] =
        make_uint4(rr[0], rr[1], rr[2], rr[3]);
}

// ---------------------------------------------------------------------------
// Activation split+transpose: x[b][ci][pos] f32 -> xh/xl[b][pos][ci] bf16.
// ---------------------------------------------------------------------------
__global__ void xsplitT(const float* __restrict__ x, unsigned short* __restrict__ xh,
                        unsigned short* __restrict__ xl) {
    __shared__ float s[32][33];
    int b = blockIdx.z, pt = blockIdx.x, ct = blockIdx.y;
    int tx = threadIdx.x, ty = threadIdx.y;
#pragma unroll
    for (int i = 0; i < 4; i++) {
        int ci = (ct << 5) + ty + (i << 3);
        int pos = (pt << 5) + tx;
        s[ty + (i << 3)][tx] = x[(((size_t)(b << 8) + ci) << 10) + pos];
    }
    __syncthreads();
#pragma unroll
    for (int i = 0; i < 4; i++) {
        int pos = (pt << 5) + ty + (i << 3);
        int ci = (ct << 5) + tx;
        float v = s[tx][ty + (i << 3)];
        __nv_bfloat16 hb = __float2bfloat16(v);
        __nv_bfloat16 lb = __float2bfloat16(v - __bfloat162float(hb));
        size_t o = (((size_t)b << 10) + pos) * 256 + ci;
        xh[o] = __bfloat16_as_ushort(hb);
        xl[o] = __bfloat16_as_ushort(lb);
    }
}

// ---------------------------------------------------------------------------
// Zero pad rows [CK, CKp) of col buffer, per batch
// ---------------------------------------------------------------------------
__global__ void zero_pad_rows(float* __restrict__ col, int B, int CK, int CKp, int HW) {
    int rows = CKp - CK;
    int t = blockIdx.x * THREADS + threadIdx.x;
    int total = B * rows * HW;
    if (t >= total) return;
    int pos = t % HW;
    int rest = t / HW;
    int r = rest % rows;
    int b = rest / rows;
    col[((size_t)b * CKp + CK + r) * HW + pos] = 0.f;
}

// ---------------------------------------------------------------------------
// Templated deform im2col (unchanged, proven)
// ---------------------------------------------------------------------------
template <int Cin, int CIG, int K, int KW, int S, int P, int Hd, int Wd, int Wo, int HW>
__global__ void build_deform_t(const float* __restrict__ x, const float* __restrict__ om,
                               float* __restrict__ col, int CKp) {
    constexpr int G = Cin / CIG;
    constexpr int Q = HW / 4;
    int t = blockIdx.x * THREADS + threadIdx.x;
    if (t >= 16 * G * K * Q) return;
    int q = t % Q;  int rest = t / Q;
    int k = rest % K; rest /= K;
    int g = rest % G;
    int b = rest / G;

    int pos = q * 4;
    int ho = pos / Wo;
    int wo = pos % Wo;

    const float* omb = om + (size_t)b * 3 * K * HW;
    float4 oy = *(const float4*)&omb[(size_t)(2 * k) * HW + pos];
    float4 ox = *(const float4*)&omb[(size_t)(2 * k + 1) * HW + pos];
    float4 mv = *(const float4*)&omb[(size_t)(2 * K + k) * HW + pos];
    float oyv[4] = {oy.x, oy.y, oy.z, oy.w};
    float oxv[4] = {ox.x, ox.y, ox.z, ox.w};
    float mkv[4] = {mv.x, mv.y, mv.z, mv.w};

    int ky = k / KW, kx = k - ky * KW;
    float by = (float)(ho * S - P + ky);

    float wgt[4][4];
    int   idx[4][4];
#pragma unroll
    for (int j = 0; j < 4; j++) {
        float mk = 1.f / (1.f + expf(-mkv[j]));
        float yf = by + oyv[j];
        float xf = (float)((wo + j) * S - P + kx) + oxv[j];
        float y0f = floorf(yf), x0f = floorf(xf);
        float dy = yf - y0f, dx = xf - x0f;
        int y0 = (int)y0f, x0 = (int)x0f;
        int y1 = y0 + 1, x1 = x0 + 1;
        bool vy0 = (y0 >= 0) & (y0 < Hd);
        bool vy1 = (y1 >= 0) & (y1 < Hd);
        bool vx0 = (x0 >= 0) & (x0 < Wd);
        bool vx1 = (x1 >= 0) & (x1 < Wd);
        float w00 = (1.f - dy) * (1.f - dx) * mk;
        float w01 = (1.f - dy) * dx * mk;
        float w10 = dy * (1.f - dx) * mk;
        float w11 = dy * dx * mk;
        wgt[j][0] = (vy0 & vx0) ? w00 : 0.f;
        wgt[j][1] = (vy0 & vx1) ? w01 : 0.f;
        wgt[j][2] = (vy1 & vx0) ? w10 : 0.f;
        wgt[j][3] = (vy1 & vx1) ? w11 : 0.f;
        int y0c = min(max(y0, 0), Hd - 1);
        int y1c = min(max(y1, 0), Hd - 1);
        int x0c = min(max(x0, 0), Wd - 1);
        int x1c = min(max(x1, 0), Wd - 1);
        idx[j][0] = y0c * Wd + x0c;
        idx[j][1] = y0c * Wd + x1c;
        idx[j][2] = y1c * Wd + x0c;
        idx[j][3] = y1c * Wd + x1c;
    }

    const float* xp = x + ((size_t)b * Cin + g * CIG) * (Hd * Wd);
    float* cb = col + ((size_t)b * CKp + (size_t)(g * CIG) * K + k) * HW + pos;
#pragma unroll 2
    for (int c = 0; c < CIG; c++) {
        float4 v;
        v.x = wgt[0][0] * xp[idx[0][0]] + wgt[0][1] * xp[idx[0][1]]
            + wgt[0][2] * xp[idx[0][2]] + wgt[0][3] * xp[idx[0][3]];
        v.y = wgt[1][0] * xp[idx[1][0]] + wgt[1][1] * xp[idx[1][1]]
            + wgt[1][2] * xp[idx[1][2]] + wgt[1][3] * xp[idx[1][3]];
        v.z = wgt[2][0] * xp[idx[2][0]] + wgt[2][1] * xp[idx[2][1]]
            + wgt[2][2] * xp[idx[2][2]] + wgt[2][3] * xp[idx[2][3]];
        v.w = wgt[3][0] * xp[idx[3][0]] + wgt[3][1] * xp[idx[3][1]]
            + wgt[3][2] * xp[idx[3][2]] + wgt[3][3] * xp[idx[3][3]];
        *(float4*)cb = v;
        xp += Hd * Wd;
        cb += (size_t)K * HW;
    }
}

// ---------------------------------------------------------------------------
// FFMA2 micro-kernel core + epilogue (gemm2 / gemm_off, unchanged)
// ---------------------------------------------------------------------------
template <int BM>
__device__ __forceinline__ void mma_tile(const float (*As)[BM], const float (*Bs)[128],
                                         unsigned long long (*acc)[4], int tx, int ty) {
    constexpr int RM = BM / 16;
#pragma unroll
    for (int kk = 0; kk < 16; kk++) {
        double2 blo = *(const double2*)&Bs[kk][tx * 4];
        double2 bhi = *(const double2*)&Bs[kk][tx * 4 + 64];
        unsigned long long bp[4];
        bp[0] = __double_as_longlong(blo.x);
        bp[1] = __double_as_longlong(blo.y);
        bp[2] = __double_as_longlong(bhi.x);
        bp[3] = __double_as_longlong(bhi.y);

        float4 a0 = *(const float4*)&As[kk][ty * 4];
        float av[RM];
        av[0] = a0.x; av[1] = a0.y; av[2] = a0.z; av[3] = a0.w;
        if (BM == 128) {
            float4 a1 = *(const float4*)&As[kk][ty * 4 + 64];
            av[4] = a1.x; av[5] = a1.y; av[6] = a1.z; av[7] = a1.w;
        }
        unsigned long long ad[RM];
#pragma unroll
        for (int i = 0; i < RM; i++)
            asm("mov.b64 %0, {%1, %1};" : "=l"(ad[i]) : "f"(av[i]));
#pragma unroll
        for (int i = 0; i < RM; i++)
#pragma unroll
            for (int j = 0; j < 4; j++)
                asm("fma.rn.f32x2 %0, %1, %2, %0;"
                    : "+l"(acc[i][j]) : "l"(ad[i]), "l"(bp[j]));
    }
}

template <int BM>
__device__ __forceinline__ void epilogue(unsigned long long (*acc)[4],
                                         const float* bias, float* Cb,
                                         int M, int N, int tM, int tN, int tx, int ty) {
    constexpr int RM = BM / 16;
#pragma unroll
    for (int i = 0; i < RM; i++) {
        int gm = tM + ((i < 4) ? (ty * 4 + i) : (64 + ty * 4 + (i - 4)));
        if (gm >= M) continue;
        float bb = bias[gm];
        float o[8];
#pragma unroll
        for (int j = 0; j < 4; j++)
            asm("mov.b64 {%0, %1}, %2;"
                : "=f"(o[2 * j]), "=f"(o[2 * j + 1]) : "l"(acc[i][j]));
        float4 s0 = make_float4(o[0] + bb, o[1] + bb, o[2] + bb, o[3] + bb);
        float4 s1 = make_float4(o[4] + bb, o[5] + bb, o[6] + bb, o[7] + bb);
        *(float4*)&Cb[(size_t)gm * N + tN + tx * 4]      = s0;
        *(float4*)&Cb[(size_t)gm * N + tN + tx * 4 + 64] = s1;
    }
}

template <int BM>
__device__ __forceinline__ void load_tiles(const float* At, const float* Bb,
                                           float (*As)[BM], float (*Bs)[128],
                                           int k0, int tM, int tN, int Mp, int N, int tid) {
#pragma unroll
    for (int it = 0; it < BM / 64; it++) {
        int f4 = tid + it * 256;
        int kk = f4 / (BM / 4);
        int m4 = (f4 % (BM / 4)) * 4;
        cpa16(&As[kk][m4], &At[(size_t)(k0 + kk) * Mp + tM + m4]);
    }
#pragma unroll
    for (int it = 0; it < 2; it++) {
        int f4 = tid + it * 256;
        int kk = f4 >> 5, c4 = (f4 & 31) * 4;
        cpa16(&Bs[kk][c4], &Bb[(size_t)(k0 + kk) * N + tN + c4]);
    }
}

template <int BM>
__global__ void __launch_bounds__(256, 2)
gemm2(const float* __restrict__ At, const float* __restrict__ Bcol,
      const float* __restrict__ bias, float* __restrict__ C,
      int M, int Mp, int Kp, int N) {
    constexpr int RM = BM / 16;
    int b = blockIdx.z;
    const float* Bb = Bcol + (size_t)b * Kp * N;
    float* Cb = C + (size_t)b * M * N;
    int tM = blockIdx.y * BM;
    int tN = blockIdx.x * 128;

    __shared__ float As[2][16][BM];
    __shared__ float Bs[2][16][128];

    int tid = threadIdx.x;
    int tx = tid & 15;
    int ty = tid >> 4;

    unsigned long long acc[RM][4];
#pragma unroll
    for (int i = 0; i < RM; i++)
#pragma unroll
        for (int j = 0; j < 4; j++) acc[i][j] = 0ULL;

    int nt = Kp >> 4;
    load_tiles<BM>(At, Bb, As[0], Bs[0], 0, tM, tN, Mp, N, tid);
    cp_commit();
    for (int i = 0; i < nt; i++) {
        if (i + 1 < nt) {
            load_tiles<BM>(At, Bb, As[(i + 1) & 1], Bs[(i + 1) & 1],
                           (i + 1) << 4, tM, tN, Mp, N, tid);
            cp_commit();
            cp_wait<1>();
        } else {
            cp_wait<0>();
        }
        __syncthreads();
        mma_tile<BM>(As[i & 1], Bs[i & 1], acc, tx, ty);
        __syncthreads();
    }
    epilogue<BM>(acc, bias, Cb, M, N, tM, tN, tx, ty);
}

template <int BM, int Cin, int KH, int KW, int S, int P, int Hd, int Wd, int WoL2>
__global__ void __launch_bounds__(256, 2)
gemm_off(const float* __restrict__ At, const float* __restrict__ x,
         const float* __restrict__ bias, float* __restrict__ C,
         int M, int Mp, int Kp, int N) {
    constexpr int RM = BM / 16;
    constexpr int CK = Cin * KH * KW;
    int b = blockIdx.z;
    const float* xb = x + (size_t)b * Cin * Hd * Wd;
    float* Cb = C + (size_t)b * M * N;
    int tM = blockIdx.y * BM;
    int tN = blockIdx.x * 128;

    __shared__ float As[2][16][BM];
    __shared__ float Bs[2][16][128];

    int tid = threadIdx.x;
    int tx = tid & 15;
    int ty = tid >> 4;

    auto load = [&](float (*As_)[BM], float (*Bs_)[128], int k0) {
#pragma unroll
        for (int it = 0; it < BM / 64; it++) {
            int f4 = tid + it * 256;
            int kk = f4 / (BM / 4);
            int m4 = (f4 % (BM / 4)) * 4;
            cpa16(&As_[kk][m4], &At[(size_t)(k0 + kk) * Mp + tM + m4]);
        }
#pragma unroll
        for (int it = 0; it < 2; it++) {
            int f4 = tid + it * 256;
            int row = f4 >> 5;
            int c4 = (f4 & 31) * 4;
            int kidx = k0 + row;
            int pos = tN + c4;
            int ho = pos >> WoL2;
            int wo = pos & ((1 << WoL2) - 1);
            if (kidx < CK) {
                int k = kidx / Cin, ci = kidx - (kidx / Cin) * Cin;
                int ky = k / KW, kx = k - ky * KW;
                int iy = ho * S - P + ky;
                bool yok = (iy >= 0) & (iy < Hd);
                const float* xr = xb + (size_t)ci * Hd * Wd + (size_t)iy * Wd;
#pragma unroll
                for (int j = 0; j < 4; j++) {
                    int ix = (wo + j) * S - P + kx;
                    if (yok && ix >= 0 && ix < Wd) cpa4(&Bs_[row][c4 + j], &xr[ix]);
                    else Bs_[row][c4 + j] = 0.f;
                }
            } else {
                *(float4*)&Bs_[row][c4] = make_float4(0.f, 0.f, 0.f, 0.f);
            }
        }
    };

    unsigned long long acc[RM][4];
#pragma unroll
    for (int i = 0; i < RM; i++)
#pragma unroll
        for (int j = 0; j < 4; j++) acc[i][j] = 0ULL;

    int nt = Kp >> 4;
    load(As[0], Bs[0], 0);
    cp_commit();
    for (int i = 0; i < nt; i++) {
        if (i + 1 < nt) {
            load(As[(i + 1) & 1], Bs[(i + 1) & 1], (i + 1) << 4);
            cp_commit();
            cp_wait<1>();
        } else {
            cp_wait<0>();
        }
        __syncthreads();
        mma_tile<BM>(As[i & 1], Bs[i & 1], acc, tx, ty);
        __syncthreads();
    }
    epilogue<BM>(acc, bias, Cb, M, N, tM, tN, tx, ty);
}

// ---------------------------------------------------------------------------
// mma.sync residual conv: 3x3 reflect, 256ch, 32x32, bf16 2-term split.
// CTA tile 128(co) x 128(pos); 8 warps = 4(M) x 2(N); K = 2304 in 144 chunks.
// ---------------------------------------------------------------------------
__device__ __forceinline__ void mma_bf16(float* c, const uint4 a, unsigned b0, unsigned b1) {
    asm volatile(
        "mma.sync.aligned.m16n8k16.row.col.f32.bf16.bf16.f32 "
        "{%0,%1,%2,%3}, {%4,%5,%6,%7}, {%8,%9}, {%0,%1,%2,%3};"
        : "+f"(c[0]), "+f"(c[1]), "+f"(c[2]), "+f"(c[3])
        : "r"(a.x), "r"(a.y), "r"(a.z), "r"(a.w), "r"(b0), "r"(b1));
}

__global__ void __launch_bounds__(256, 2)
gemm_res_mma(const uint4* __restrict__ wfrag, const unsigned short* __restrict__ xh,
             const unsigned short* __restrict__ xl, const float* __restrict__ bias,
             float* __restrict__ C) {
    __shared__ __align__(16) unsigned short Bsm[2][2][2048];  // [stage][hi/lo][128n x 16k]
    int tid = threadIdx.x;
    int wid = tid >> 5, lane = tid & 31;
    int wn = wid >> 2, wm = wid & 3;
    int g = lane >> 2, q = lane & 3;
    int tN = blockIdx.x << 7;
    int mt = blockIdx.y;
    int b  = blockIdx.z;

    const unsigned short* xsh = xh + ((size_t)b << 18);
    const unsigned short* xsl = xl + ((size_t)b << 18);
    unsigned sb = (unsigned)__cvta_generic_to_shared(&Bsm[0][0][0]);

    float acc[2][8][4];
#pragma unroll
    for (int i = 0; i < 2; i++)
#pragma unroll
        for (int j = 0; j < 8; j++)
#pragma unroll
            for (int e = 0; e < 4; e++) acc[i][j][e] = 0.f;

    int bn = tid & 127, bpart = tid >> 7;
    const unsigned short* bsrc = bpart ? xsl : xsh;

    auto buildB = [&](int stage, int c) {
        int tap = c >> 4;
        int ci0 = (c & 15) << 4;
        int dy = tap / 3 - 1, dx = tap - (tap / 3) * 3 - 1;
        int p = tN + bn;
        int py = (p >> 5) + dy; py = py < 0 ? -py : (py > 31 ? 62 - py : py);
        int px = (p & 31) + dx; px = px < 0 ? -px : (px > 31 ? 62 - px : px);
        const unsigned short* src = bsrc + (size_t)((py << 5) + px) * 256 + ci0;
        unsigned dbase = sb + (unsigned)(stage * 8192 + bpart * 4096);
        unsigned xr = (unsigned)((bn & 4) << 2);
        cpa16_s(dbase + ((unsigned)(bn * 32) ^ xr), src);
        cpa16_s(dbase + ((unsigned)(bn * 32 + 16) ^ xr), src + 8);
    };

    buildB(0, 0);
    cp_commit();

    int mg0 = (mt << 3) + (wm << 1);
    const char* bsm0 = (const char*)&Bsm[0][0][0];

    for (int c = 0; c < 144; c++) {
        size_t i0 = ((size_t)mg0 * 144 + c) * 32 + lane;
        size_t i1 = ((size_t)(mg0 + 1) * 144 + c) * 32 + lane;
        uint4 ah0 = __ldg(&wfrag[i0]);
        uint4 ah1 = __ldg(&wfrag[i1]);
        uint4 al0 = __ldg(&wfrag[73728 + i0]);
        uint4 al1 = __ldg(&wfrag[73728 + i1]);
        if (c + 1 < 144) { buildB((c + 1) & 1, c + 1); cp_commit(); cp_wait<1>(); }
        else cp_wait<0>();
        __syncthreads();
        const char* st = bsm0 + ((c & 1) << 13);
#pragma unroll
        for (int nt = 0; nt < 8; nt++) {
            int n = (wn << 6) + (nt << 3) + g;
            unsigned xr = (unsigned)((n & 4) << 2);
            unsigned o0 = (unsigned)(n * 32 + q * 4) ^ xr;
            unsigned o1 = (unsigned)(n * 32 + 16 + q * 4) ^ xr;
            unsigned bh0 = *(const unsigned*)(st + o0);
            unsigned bh1 = *(const unsigned*)(st + o1);
            unsigned bl0 = *(const unsigned*)(st + 4096 + o0);
            unsigned bl1 = *(const unsigned*)(st + 4096 + o1);
            mma_bf16(acc[0][nt], ah0, bh0, bh1);
            mma_bf16(acc[1][nt], ah1, bh0, bh1);
            mma_bf16(acc[0][nt], al0, bh0, bh1);
            mma_bf16(acc[1][nt], al1, bh0, bh1);
            mma_bf16(acc[0][nt], ah0, bl0, bl1);
            mma_bf16(acc[1][nt], ah1, bl0, bl1);
        }
        __syncthreads();
    }

    // epilogue
#pragma unroll
    for (int sub = 0; sub < 2; sub++) {
        int co = (mt << 7) + (wm << 5) + (sub << 4) + g;
        float bb0 = bias[co], bb1 = bias[co + 8];
        float* o0 = C + (((size_t)(b << 8) + co) << 10);
        float* o1 = o0 + (8 << 10);
#pragma unroll
        for (int nt = 0; nt < 8; nt++) {
            int col = tN + (wn << 6) + (nt << 3) + (q << 1);
            *(float2*)&o0[col] = make_float2(acc[sub][nt][0] + bb0, acc[sub][nt][1] + bb0);
            *(float2*)&o1[col] = make_float2(acc[sub][nt][2] + bb1, acc[sub][nt][3] + bb1);
        }
    }
}

// ---------------------------------------------------------------------------
// InstanceNorm (unchanged)
// ---------------------------------------------------------------------------
__global__ void instnorm(const float* __restrict__ in, float* __restrict__ out,
                         float* __restrict__ out2, const float* __restrict__ addsrc,
                         int HW, int relu) {
    int plane = blockIdx.x;
    const float* p = in + (size_t)plane * HW;
    __shared__ float ssum[THREADS];
    __shared__ float ssq[THREADS];
    int tid = threadIdx.x;
    float s = 0.f, sq = 0.f;
    for (int i = tid; i < HW; i += THREADS) {
        float v = p[i];
        s += v; sq += v * v;
    }
    ssum[tid] = s; ssq[tid] = sq;
    __syncthreads();
    for (int off = THREADS / 2; off > 0; off >>= 1) {
        if (tid < off) { ssum[tid] += ssum[tid + off]; ssq[tid] += ssq[tid + off]; }
        __syncthreads();
    }
    __shared__ float mu_s, rs_s;
    if (tid == 0) {
        float mu = ssum[0] / (float)HW;
        float var = ssq[0] / (float)HW - mu * mu;
        mu_s = mu;
        rs_s = rsqrtf(var + 1e-5f);
    }
    __syncthreads();
    float mu = mu_s, rs = rs_s;
    float* o = out + (size_t)plane * HW;
    for (int i = tid; i < HW; i += THREADS) {
        float v = (p[i] - mu) * rs;
        if (relu) v = fmaxf(v, 0.f);
        if (addsrc) v += addsrc[(size_t)plane * HW + i];
        o[i] = v;
        if (out2) out2[(size_t)plane * HW + i] = v;
    }
}

// ---------------------------------------------------------------------------
// Host orchestration
// ---------------------------------------------------------------------------
static inline int ceil_div(int a, int b) { return (a + b - 1) / b; }

extern "C" void kernel_launch(void* const* d_in, const int* in_sizes, int n_in,
                              void* d_out, int out_size) {
    (void)in_sizes; (void)n_in; (void)out_size;
    const float* x      = (const float*)d_in[0];
    const float* w_off1 = (const float*)d_in[1];
    const float* b_off1 = (const float*)d_in[2];
    const float* w1     = (const float*)d_in[3];
    const float* b1     = (const float*)d_in[4];
    const float* w_off2 = (const float*)d_in[5];
    const float* b_off2 = (const float*)d_in[6];
    const float* w2     = (const float*)d_in[7];
    const float* b2     = (const float*)d_in[8];
    const float* w_off3 = (const float*)d_in[9];
    const float* b_off3 = (const float*)d_in[10];
    const float* w3     = (const float*)d_in[11];
    const float* b3     = (const float*)d_in[12];
    const float* rw0a   = (const float*)d_in[13];
    const float* rb0a   = (const float*)d_in[14];
    const float* rw0b   = (const float*)d_in[15];
    const float* rb0b   = (const float*)d_in[16];
    const float* rw1a   = (const float*)d_in[17];
    const float* rb1a   = (const float*)d_in[18];
    const float* rw1b   = (const float*)d_in[19];
    const float* rb1b   = (const float*)d_in[20];
    float* out = (float*)d_out;

    float *col, *om, *h, *pre, *yb, *wT;
    unsigned short *xhp, *xlp;
    uint4* wfrag;
    cudaGetSymbolAddress((void**)&col, g_col);
    cudaGetSymbolAddress((void**)&om,  g_om);
    cudaGetSymbolAddress((void**)&h,   g_h);
    cudaGetSymbolAddress((void**)&pre, g_pre);
    cudaGetSymbolAddress((void**)&yb,  g_y);
    cudaGetSymbolAddress((void**)&wT,  g_wT);
    cudaGetSymbolAddress((void**)&xhp, g_xh);
    cudaGetSymbolAddress((void**)&xlp, g_xl);
    cudaGetSymbolAddress((void**)&wfrag, g_wfrag);

    const int B = 16;

    // ---------------- Layer 1: 3 -> 64, 7x7 s1 p3, 128x128 -> 128x128 ------
    {
        const int HW = 16384, CK = 147, CKp = 160;
        transpose_off<<<ceil_div(160 * 192, THREADS), THREADS>>>(w_off1, wT, 147, 3, 49, 192, 160);
        gemm_off<64, 3, 7, 7, 1, 3, 128, 128, 7><<<dim3(HW / 128, 3, B), 256>>>(
            wT, x, b_off1, om, 147, 192, 160, HW);
        build_deform_t<3, 3, 49, 7, 1, 3, 128, 128, 128, 16384>
            <<<ceil_div(B * 49 * (HW / 4), THREADS), THREADS>>>(x, om, col, CKp);
        zero_pad_rows<<<ceil_div(B * (CKp - CK) * HW, THREADS), THREADS>>>(col, B, CK, CKp, HW);
        transpose_pad<<<ceil_div(160 * 64, THREADS), THREADS>>>(w1, wT, 64, 147, 64, 160);
        gemm2<64><<<dim3(HW / 128, 1, B), 256>>>(wT, col, b1, pre, 64, 64, CKp, HW);
        instnorm<<<B * 64, THREADS>>>(pre, h, nullptr, nullptr, HW, 1);
    }
    // ---------------- Layer 2: 64 -> 128, 4x4 s2 p1, 128 -> 64 -------------
    {
        const int HW = 4096, CK = 1024;
        transpose_off<<<ceil_div(1024 * 64, THREADS), THREADS>>>(w_off2, wT, 48, 64, 16, 64, 1024);
        gemm_off<64, 64, 4, 4, 2, 1, 128, 128, 6><<<dim3(HW / 128, 1, B), 256>>>(
            wT, h, b_off2, om, 48, 64, 1024, HW);
        build_deform_t<64, 16, 16, 4, 2, 1, 128, 128, 64, 4096>
            <<<ceil_div(B * 4 * 16 * (HW / 4), THREADS), THREADS>>>(h, om, col, CK);
        transpose_pad<<<ceil_div(1024 * 128, THREADS), THREADS>>>(w2, wT, 128, 1024, 128, 1024);
        gemm2<128><<<dim3(HW / 128, 1, B), 256>>>(wT, col, b2, pre, 128, 128, CK, HW);
        instnorm<<<B * 128, THREADS>>>(pre, h, out + 4194304, nullptr, HW, 1);  // skip2
    }
    // ---------------- Layer 3: 128 -> 256, 4x4 s2 p1, 64 -> 32 -------------
    {
        const int HW = 1024, CK = 2048;
        transpose_off<<<ceil_div(2048 * 64, THREADS), THREADS>>>(w_off3, wT, 48, 128, 16, 64, 2048);
        gemm_off<64, 128, 4, 4, 2, 1, 64, 64, 5><<<dim3(HW / 128, 1, B), 256>>>(
            wT, h, b_off3, om, 48, 64, 2048, HW);
        build_deform_t<128, 16, 16, 4, 2, 1, 64, 64, 32, 1024>
            <<<ceil_div(B * 8 * 16 * (HW / 4), THREADS), THREADS>>>(h, om, col, CK);
        transpose_pad<<<ceil_div(2048 * 256, THREADS), THREADS>>>(w3, wT, 256, 2048, 256, 2048);
        gemm2<128><<<dim3(HW / 128, 2, B), 256>>>(wT, col, b3, pre, 256, 256, CK, HW);
        instnorm<<<B * 256, THREADS>>>(pre, h, out + 12582912, nullptr, HW, 1); // skip3
    }
    // ---------------- Residual blocks: mma.sync bf16-split implicit GEMM ----
    {
        const int HW = 1024, C = 256;
        const float* wa[2]  = { rw0a, rw1a };
        const float* ba[2]  = { rb0a, rb1a };
        const float* wb[2]  = { rw0b, rw1b };
        const float* bbv[2] = { rb0b, rb1b };
        for (int r = 0; r < 2; r++) {
            w_split_frag<<<576, THREADS>>>(wa[r], wfrag);
            xsplitT<<<dim3(32, 8, 16), dim3(32, 8)>>>(h, xhp, xlp);
            gemm_res_mma<<<dim3(8, 2, B), 256>>>(wfrag, xhp, xlp, ba[r], pre);
            instnorm<<<B * C, THREADS>>>(pre, yb, nullptr, nullptr, HW, 1);
            w_split_frag<<<576, THREADS>>>(wb[r], wfrag);
            xsplitT<<<dim3(32, 8, 16), dim3(32, 8)>>>(yb, xhp, xlp);
            gemm_res_mma<<<dim3(8, 2, B), 256>>>(wfrag, xhp, xlp, bbv[r], pre);
            float* dst = (r == 0) ? h : out;   // final h goes straight to d_out
            instnorm<<<B * C, THREADS>>>(pre, dst, nullptr, h, HW, 0);
        }
    }
}